// round 8
// baseline (speedup 1.0000x reference)
#include <cuda_runtime.h>
#include <cuda_bf16.h>
#include <math.h>
#include <stdint.h>

// ---------------- problem dims (fixed) ----------------
#define Bb   4
#define Tt   1024
#define Dd   1024
#define Hh   16
#define HSs  64
#define DFF  4096
#define ROWS (Bb*Tt)      // 4096

// ---------------- scratch (device globals; no allocs allowed) ----------------
__device__ float g_hn [ROWS*Dd];
__device__ float g_q  [ROWS*2048];
__device__ float g_k  [ROWS*2048];
__device__ float g_v  [ROWS*1024];
__device__ float g_h2 [ROWS*Dd];
__device__ float g_m1 [ROWS*DFF];
__device__ float g_m2 [ROWS*DFF];
__device__ float g_lam[32];

// bf16 hi/lo split buffers
#define NW_TOT (24u*1024u*1024u)
__device__ __nv_bfloat16 g_whi[NW_TOT];
__device__ __nv_bfloat16 g_wlo[NW_TOT];
#define NA_TOT (ROWS*DFF)
__device__ __nv_bfloat16 g_ahi[NA_TOT];
__device__ __nv_bfloat16 g_alo[NA_TOT];
#define NB_TOT (ROWS*1024)
__device__ __nv_bfloat16 g_bhi[NB_TOT];
__device__ __nv_bfloat16 g_blo[NB_TOT];

// weight offsets (elements)
#define OW_QS (0u)
#define OW_KS (2u*1024u*1024u)
#define OW_VS (4u*1024u*1024u)
#define OW_OS (5u*1024u*1024u)
#define OW_QC (6u*1024u*1024u)
#define OW_KC (8u*1024u*1024u)
#define OW_VC (10u*1024u*1024u)
#define OW_OC (11u*1024u*1024u)
#define OW_W1 (12u*1024u*1024u)
#define OW_W2 (16u*1024u*1024u)
#define OW_W3 (20u*1024u*1024u)

// ================= small helpers =================
__device__ __forceinline__ uint32_t smem_u32(const void* p) {
    uint32_t a;
    asm("{ .reg .u64 t; cvta.to.shared.u64 t, %1; cvt.u32.u64 %0, t; }" : "=r"(a) : "l"(p));
    return a;
}
__device__ __forceinline__ void cp16(uint32_t dst, const void* src) {
    asm volatile("cp.async.cg.shared.global [%0], [%1], 16;" :: "r"(dst), "l"(src) : "memory");
}
__device__ __forceinline__ void cp_commit() {
    asm volatile("cp.async.commit_group;" ::: "memory");
}
__device__ __forceinline__ void cp_wait2() {
    asm volatile("cp.async.wait_group 2;" ::: "memory");
}
__device__ __forceinline__ void mma16816(float* d, const uint32_t* a, const uint32_t* b) {
    asm volatile(
        "mma.sync.aligned.m16n8k16.row.col.f32.bf16.bf16.f32 "
        "{%0,%1,%2,%3}, {%4,%5,%6,%7}, {%8,%9}, {%0,%1,%2,%3};"
        : "+f"(d[0]), "+f"(d[1]), "+f"(d[2]), "+f"(d[3])
        : "r"(a[0]), "r"(a[1]), "r"(a[2]), "r"(a[3]), "r"(b[0]), "r"(b[1]));
}

// ============ activation split: fp32 -> bf16 hi + bf16 lo ============
__global__ __launch_bounds__(256) void split_kernel(
    const float4* __restrict__ in, __nv_bfloat162* __restrict__ hi,
    __nv_bfloat162* __restrict__ lo, int n4)
{
    const int i = blockIdx.x * blockDim.x + threadIdx.x;
    if (i >= n4) return;
    float4 v = in[i];
    __nv_bfloat162 h01 = __floats2bfloat162_rn(v.x, v.y);
    __nv_bfloat162 h23 = __floats2bfloat162_rn(v.z, v.w);
    float2 f01 = __bfloat1622float2(h01);
    float2 f23 = __bfloat1622float2(h23);
    __nv_bfloat162 l01 = __floats2bfloat162_rn(v.x - f01.x, v.y - f01.y);
    __nv_bfloat162 l23 = __floats2bfloat162_rn(v.z - f23.x, v.w - f23.y);
    hi[2*i] = h01; hi[2*i+1] = h23;
    lo[2*i] = l01; lo[2*i+1] = l23;
}

// ============ weight split + transpose: B[K][N] fp32 -> Bt[N][K] bf16 hi/lo ============
__global__ __launch_bounds__(256) void split_t_kernel(
    const float* __restrict__ B, __nv_bfloat16* __restrict__ thi,
    __nv_bfloat16* __restrict__ tlo, int K, int N)
{
    __shared__ float tile[32][33];
    const int tx = threadIdx.x, ty = threadIdx.y;
    const int n0 = blockIdx.x * 32, k0 = blockIdx.y * 32;
#pragma unroll
    for (int j = ty; j < 32; j += 8)
        tile[j][tx] = B[(size_t)(k0 + j) * N + n0 + tx];
    __syncthreads();
#pragma unroll
    for (int j = ty; j < 32; j += 8) {
        float x = tile[tx][j];
        __nv_bfloat16 h = __float2bfloat16(x);
        __nv_bfloat16 l = __float2bfloat16(x - __bfloat162float(h));
        const size_t o = (size_t)(n0 + j) * K + k0 + tx;
        thi[o] = h; tlo[o] = l;
    }
}

// ============ bf16x3 tensor-core GEMM (R5-proven mainloop) + optional split epilogue ============
#define BG_ROWB   80
#define BG_BUF    (128*BG_ROWB)
#define BG_STAGE  (4*BG_BUF)
#define BG_SMEM   (3*BG_STAGE)

__global__ __launch_bounds__(256) void bgemm_kernel(
    const __nv_bfloat16* __restrict__ Ahi, const __nv_bfloat16* __restrict__ Alo,
    const __nv_bfloat16* __restrict__ Bhi, const __nv_bfloat16* __restrict__ Blo,
    const float* __restrict__ R, float* __restrict__ Cf,
    __nv_bfloat16* __restrict__ Chi, __nv_bfloat16* __restrict__ Clo,
    int M, int N, int K, int mode)
{
    extern __shared__ char sm_c[];
    const uint32_t smb = smem_u32(sm_c);

    const int tid = threadIdx.x;
    const int wid = tid >> 5;
    const int lane = tid & 31;
    const int bm = blockIdx.y * 128, bn = blockIdx.x * 128;
    const int m0 = (wid >> 2) * 64;
    const int n0 = (wid & 3) * 32;
    const int qrow = lane >> 2;
    const int qk4 = (lane & 3) * 4;

    const int nch = K >> 5;

    auto issue_stage = [&](int t) {
        const int k0 = t * 32;
        const uint32_t sb = smb + (uint32_t)(t % 3) * BG_STAGE;
#pragma unroll
        for (int c = 0; c < 2; ++c) {
            const int idx = tid + c * 256;
            const int row = idx >> 2, q = idx & 3;
            const uint32_t so = (uint32_t)row * BG_ROWB + q * 16;
            const size_t goA = (size_t)(bm + row) * K + k0 + q * 8;
            const size_t goB = (size_t)(bn + row) * K + k0 + q * 8;
            cp16(sb + so,            Ahi + goA);
            cp16(sb + BG_BUF + so,   Alo + goA);
            cp16(sb + 2*BG_BUF + so, Bhi + goB);
            cp16(sb + 3*BG_BUF + so, Blo + goB);
        }
        cp_commit();
    };

    issue_stage(0); issue_stage(1); issue_stage(2);

    float acc[4][4][4];
#pragma unroll
    for (int a = 0; a < 4; ++a)
#pragma unroll
        for (int b = 0; b < 4; ++b)
#pragma unroll
            for (int c = 0; c < 4; ++c) acc[a][b][c] = 0.f;

    for (int t = 0; t < nch; ++t) {
        cp_wait2();
        __syncthreads();
        const char* Ah = sm_c + (t % 3) * BG_STAGE;
        const char* Al = Ah + BG_BUF;
        const char* Bh = Ah + 2*BG_BUF;
        const char* Bl = Ah + 3*BG_BUF;
#pragma unroll
        for (int kb = 0; kb <= 32; kb += 32) {
            uint32_t ahi[4][4], alo[4][4], bhi[4][2], blo[4][2];
#pragma unroll
            for (int mt = 0; mt < 4; ++mt) {
                const uint32_t off = (uint32_t)(m0 + mt*16 + qrow) * BG_ROWB + kb + qk4;
                ahi[mt][0] = *(const uint32_t*)(Ah + off);
                ahi[mt][1] = *(const uint32_t*)(Ah + off + 8*BG_ROWB);
                ahi[mt][2] = *(const uint32_t*)(Ah + off + 16);
                ahi[mt][3] = *(const uint32_t*)(Ah + off + 8*BG_ROWB + 16);
                alo[mt][0] = *(const uint32_t*)(Al + off);
                alo[mt][1] = *(const uint32_t*)(Al + off + 8*BG_ROWB);
                alo[mt][2] = *(const uint32_t*)(Al + off + 16);
                alo[mt][3] = *(const uint32_t*)(Al + off + 8*BG_ROWB + 16);
            }
#pragma unroll
            for (int nt = 0; nt < 4; ++nt) {
                const uint32_t off = (uint32_t)(n0 + nt*8 + qrow) * BG_ROWB + kb + qk4;
                bhi[nt][0] = *(const uint32_t*)(Bh + off);
                bhi[nt][1] = *(const uint32_t*)(Bh + off + 16);
                blo[nt][0] = *(const uint32_t*)(Bl + off);
                blo[nt][1] = *(const uint32_t*)(Bl + off + 16);
            }
#pragma unroll
            for (int mt = 0; mt < 4; ++mt)
#pragma unroll
                for (int nt = 0; nt < 4; ++nt) {
                    mma16816(acc[mt][nt], ahi[mt], bhi[nt]);
                    mma16816(acc[mt][nt], ahi[mt], blo[nt]);
                    mma16816(acc[mt][nt], alo[mt], bhi[nt]);
                }
        }
        __syncthreads();
        if (t + 3 < nch) issue_stage(t + 3);
        else cp_commit();
    }

    // ---- epilogue ----
#pragma unroll
    for (int mt = 0; mt < 4; ++mt) {
        const int r0 = bm + m0 + mt*16 + qrow;
#pragma unroll
        for (int nt = 0; nt < 4; ++nt) {
            const int c = bn + n0 + nt*8 + (lane & 3) * 2;
            float2 v0 = make_float2(acc[mt][nt][0], acc[mt][nt][1]);
            float2 v1 = make_float2(acc[mt][nt][2], acc[mt][nt][3]);
            if (mode == 1) {
                const float* q0 = R + (size_t)r0 * N + c;
                const float* q1 = R + (size_t)(r0 + 8) * N + c;
                v0.x += q0[0]; v0.y += q0[1];
                v1.x += q1[0]; v1.y += q1[1];
            } else if (mode == 2) {
                v0.x *= 2.f; v0.y *= 2.f; v1.x *= 2.f; v1.y *= 2.f;
            }
            if (Cf) {
                *(float2*)(Cf + (size_t)r0 * N + c) = v0;
                *(float2*)(Cf + (size_t)(r0 + 8) * N + c) = v1;
            }
            if (Chi) {
                __nv_bfloat162 h0 = __floats2bfloat162_rn(v0.x, v0.y);
                __nv_bfloat162 h1 = __floats2bfloat162_rn(v1.x, v1.y);
                float2 f0 = __bfloat1622float2(h0);
                float2 f1 = __bfloat1622float2(h1);
                __nv_bfloat162 l0 = __floats2bfloat162_rn(v0.x - f0.x, v0.y - f0.y);
                __nv_bfloat162 l1 = __floats2bfloat162_rn(v1.x - f1.x, v1.y - f1.y);
                *(__nv_bfloat162*)(Chi + (size_t)r0 * N + c) = h0;
                *(__nv_bfloat162*)(Chi + (size_t)(r0 + 8) * N + c) = h1;
                *(__nv_bfloat162*)(Clo + (size_t)r0 * N + c) = l0;
                *(__nv_bfloat162*)(Clo + (size_t)(r0 + 8) * N + c) = l1;
            }
        }
    }
}

// ---------------- helpers ----------------
__device__ __forceinline__ float red_max16(float v) {
#pragma unroll
    for (int o = 8; o; o >>= 1) v = fmaxf(v, __shfl_xor_sync(0xffffffffu, v, o));
    return v;
}
__device__ __forceinline__ float red_sum16(float v) {
#pragma unroll
    for (int o = 8; o; o >>= 1) v += __shfl_xor_sync(0xffffffffu, v, o);
    return v;
}

// ---------------- rmsnorm: fp32 out (optional) + fused hi/lo split ----------------
__global__ __launch_bounds__(256) void rmsnorm_kernel(
    const float* __restrict__ x, const float* __restrict__ g,
    float* __restrict__ outf, __nv_bfloat162* __restrict__ hi,
    __nv_bfloat162* __restrict__ lo)
{
    __shared__ float red[8];
    __shared__ float sscale;
    const int row = blockIdx.x;
    const int t = threadIdx.x;
    const float4* xr = (const float4*)(x + (size_t)row * 1024);
    float4 v = xr[t];
    float ss = v.x*v.x + v.y*v.y + v.z*v.z + v.w*v.w;
#pragma unroll
    for (int o = 16; o; o >>= 1) ss += __shfl_xor_sync(0xffffffffu, ss, o);
    if ((t & 31) == 0) red[t >> 5] = ss;
    __syncthreads();
    if (t == 0) {
        float s = 0.f;
#pragma unroll
        for (int i = 0; i < 8; ++i) s += red[i];
        sscale = rsqrtf(s * (1.0f/1024.0f) + 1e-6f);
    }
    __syncthreads();
    const float sc = sscale;
    float4 gv = ((const float4*)g)[t];
    float4 o;
    o.x = v.x*sc*gv.x; o.y = v.y*sc*gv.y; o.z = v.z*sc*gv.z; o.w = v.w*sc*gv.w;
    if (outf) ((float4*)(outf + (size_t)row * 1024))[t] = o;
    __nv_bfloat162 h01 = __floats2bfloat162_rn(o.x, o.y);
    __nv_bfloat162 h23 = __floats2bfloat162_rn(o.z, o.w);
    float2 f01 = __bfloat1622float2(h01);
    float2 f23 = __bfloat1622float2(h23);
    __nv_bfloat162 l01 = __floats2bfloat162_rn(o.x - f01.x, o.y - f01.y);
    __nv_bfloat162 l23 = __floats2bfloat162_rn(o.z - f23.x, o.w - f23.y);
    const size_t p = (size_t)row * 512 + t * 2;
    hi[p] = h01; hi[p+1] = h23;
    lo[p] = l01; lo[p+1] = l23;
}

// ---------------- lambda ----------------
__global__ void lambda_kernel(const float* __restrict__ lq1, const float* __restrict__ lk1,
                              const float* __restrict__ lq2, const float* __restrict__ lk2,
                              float* __restrict__ lam)
{
    const int h = blockIdx.x;
    const int lane = threadIdx.x;
    float s1 = 0.f, s2 = 0.f;
    for (int d = lane; d < 64; d += 32) {
        s1 += lq1[h*64 + d] * lk1[h*64 + d];
        s2 += lq2[h*64 + d] * lk2[h*64 + d];
    }
#pragma unroll
    for (int o = 16; o; o >>= 1) {
        s1 += __shfl_xor_sync(0xffffffffu, s1, o);
        s2 += __shfl_xor_sync(0xffffffffu, s2, o);
    }
    if (lane == 0) lam[h] = expf(s1) - expf(s2) + 0.8f;
}

// ---------------- flash diff-attention (fp32 compute, split-bf16 output) ----------------
#define FL_SMEM ((4*64*68 + 64*64) * 4)

__global__ __launch_bounds__(256) void flash_diff_kernel(
    const float* __restrict__ Q, const float* __restrict__ Kg,
    const float* __restrict__ Vg, const float* __restrict__ lamp,
    __nv_bfloat16* __restrict__ Ohi, __nv_bfloat16* __restrict__ Olo,
    int Sq, int Sk, int causal)
{
    extern __shared__ float sm[];
    float* Qs1 = sm;
    float* Qs2 = Qs1 + 64*68;
    float* KP1 = Qs2 + 64*68;
    float* KP2 = KP1 + 64*68;
    float* Vs  = KP2 + 64*68;

    const int tid = threadIdx.x;
    const int tx = tid & 15, ty = tid >> 4;
    const int qt = blockIdx.x, h = blockIdx.y, b = blockIdx.z;

    {
        const int r = tid >> 2;
        const int d0 = (tid & 3) << 4;
        const float* qb = Q + ((size_t)(b*Sq + qt*64 + r) * Hh + h) * 128 + d0;
#pragma unroll
        for (int u = 0; u < 16; u += 4) {
            *(float4*)&Qs1[r*68 + d0 + u] = *(const float4*)(qb + u);
            *(float4*)&Qs2[r*68 + d0 + u] = *(const float4*)(qb + 64 + u);
        }
    }

    float O1[4][4], O2[4][4];
    float rm1[4], rl1[4], rm2[4], rl2[4];
#pragma unroll
    for (int i = 0; i < 4; ++i) {
        rm1[i] = rm2[i] = -1e30f; rl1[i] = rl2[i] = 0.f;
#pragma unroll
        for (int j = 0; j < 4; ++j) { O1[i][j] = 0.f; O2[i][j] = 0.f; }
    }
    const float scale = 0.125f;
    const int nkt = causal ? (qt + 1) : (Sk >> 6);

    for (int kt = 0; kt < nkt; ++kt) {
        __syncthreads();
        {
            const int c = tid >> 2;
            const int d0 = (tid & 3) << 4;
            const float* kb = Kg + ((size_t)(b*Sk + kt*64 + c) * Hh + h) * 128 + d0;
            const float* vb = Vg + ((size_t)(b*Sk + kt*64 + c) * Hh + h) * 64 + d0;
#pragma unroll
            for (int u = 0; u < 16; u += 4) {
                *(float4*)&KP1[c*68 + d0 + u] = *(const float4*)(kb + u);
                *(float4*)&KP2[c*68 + d0 + u] = *(const float4*)(kb + 64 + u);
                *(float4*)&Vs [c*64 + d0 + u] = *(const float4*)(vb + u);
            }
        }
        __syncthreads();

        float s1[4][4], s2[4][4];
#pragma unroll
        for (int i = 0; i < 4; ++i)
#pragma unroll
            for (int j = 0; j < 4; ++j) { s1[i][j] = 0.f; s2[i][j] = 0.f; }

#pragma unroll 4
        for (int k4 = 0; k4 < 64; k4 += 4) {
            float4 qa[4], qb[4], ka[4], kb[4];
#pragma unroll
            for (int i = 0; i < 4; ++i) {
                qa[i] = *(const float4*)&Qs1[(ty*4+i)*68 + k4];
                qb[i] = *(const float4*)&Qs2[(ty*4+i)*68 + k4];
            }
#pragma unroll
            for (int j = 0; j < 4; ++j) {
                ka[j] = *(const float4*)&KP1[(j*16+tx)*68 + k4];
                kb[j] = *(const float4*)&KP2[(j*16+tx)*68 + k4];
            }
#pragma unroll
            for (int i = 0; i < 4; ++i)
#pragma unroll
                for (int j = 0; j < 4; ++j) {
                    s1[i][j] += qa[i].x*ka[j].x + qa[i].y*ka[j].y + qa[i].z*ka[j].z + qa[i].w*ka[j].w;
                    s2[i][j] += qb[i].x*kb[j].x + qb[i].y*kb[j].y + qb[i].z*kb[j].z + qb[i].w*kb[j].w;
                }
        }

        const bool maskdiag = (causal != 0) && (kt == qt);
        __syncthreads();

#pragma unroll
        for (int i = 0; i < 4; ++i) {
            const int r = ty*4 + i;
            float tm = -1e30f;
#pragma unroll
            for (int j = 0; j < 4; ++j) {
                s1[i][j] *= scale;
                if (maskdiag && (j*16 + tx) > r) s1[i][j] = -1e9f;
                tm = fmaxf(tm, s1[i][j]);
            }
            tm = red_max16(tm);
            float mn = fmaxf(rm1[i], tm);
            float al = __expf(rm1[i] - mn);
            rm1[i] = mn;
            float rs = 0.f;
#pragma unroll
            for (int j = 0; j < 4; ++j) {
                float p = __expf(s1[i][j] - mn);
                rs += p;
                KP1[r*68 + j*16 + tx] = p;
            }
            rs = red_sum16(rs);
            rl1[i] = rl1[i]*al + rs;
#pragma unroll
            for (int j = 0; j < 4; ++j) O1[i][j] *= al;

            float tm2 = -1e30f;
#pragma unroll
            for (int j = 0; j < 4; ++j) {
                s2[i][j] *= scale;
                if (maskdiag && (j*16 + tx) > r) s2[i][j] = -1e9f;
                tm2 = fmaxf(tm2, s2[i][j]);
            }
            tm2 = red_max16(tm2);
            float mn2 = fmaxf(rm2[i], tm2);
            float al2 = __expf(rm2[i] - mn2);
            rm2[i] = mn2;
            float rs2 = 0.f;
#pragma unroll
            for (int j = 0; j < 4; ++j) {
                float p = __expf(s2[i][j] - mn2);
                rs2 += p;
                KP2[r*68 + j*16 + tx] = p;
            }
            rs2 = red_sum16(rs2);
            rl2[i] = rl2[i]*al2 + rs2;
#pragma unroll
            for (int j = 0; j < 4; ++j) O2[i][j] *= al2;
        }
        __syncthreads();

#pragma unroll 4
        for (int c4 = 0; c4 < 64; c4 += 4) {
            float4 pa[4], pb[4];
#pragma unroll
            for (int i = 0; i < 4; ++i) {
                pa[i] = *(const float4*)&KP1[(ty*4+i)*68 + c4];
                pb[i] = *(const float4*)&KP2[(ty*4+i)*68 + c4];
            }
#pragma unroll
            for (int cc = 0; cc < 4; ++cc) {
                float vv[4];
#pragma unroll
                for (int j = 0; j < 4; ++j) vv[j] = Vs[(c4+cc)*64 + j*16 + tx];
#pragma unroll
                for (int i = 0; i < 4; ++i) {
                    const float p1v = ((const float*)&pa[i])[cc];
                    const float p2v = ((const float*)&pb[i])[cc];
#pragma unroll
                    for (int j = 0; j < 4; ++j) {
                        O1[i][j] += p1v * vv[j];
                        O2[i][j] += p2v * vv[j];
                    }
                }
            }
        }
    }

    const float lam = lamp[h];
#pragma unroll
    for (int i = 0; i < 4; ++i) {
        const float inv1 = 1.f / rl1[i];
        const float inv2 = 1.f / rl2[i];
        float o[4];
        float ss = 0.f;
#pragma unroll
        for (int j = 0; j < 4; ++j) {
            o[j] = O1[i][j]*inv1 - lam * (O2[i][j]*inv2);
            ss += o[j]*o[j];
        }
        ss = red_sum16(ss);
        const float scl = rsqrtf(ss * (1.0f/64.0f) + 1e-6f) * 0.2f;
        const int tq = qt*64 + ty*4 + i;
        const size_t ob = ((size_t)(b*Sq + tq) * Hh + h) * 64;
#pragma unroll
        for (int j = 0; j < 4; ++j) {
            const float val = o[j]*scl;
            __nv_bfloat16 hh = __float2bfloat16(val);
            Ohi[ob + j*16 + tx] = hh;
            Olo[ob + j*16 + tx] = __float2bfloat16(val - __bfloat162float(hh));
        }
    }
}

// ---------------- silu(a) * b with fused hi/lo split ----------------
__global__ void silu_mul_kernel(const float4* __restrict__ a, const float4* __restrict__ b,
                                __nv_bfloat162* __restrict__ hi, __nv_bfloat162* __restrict__ lo)
{
    const int i = blockIdx.x * blockDim.x + threadIdx.x;
    float4 av = a[i], bv = b[i], r;
    r.x = av.x / (1.f + __expf(-av.x)) * bv.x;
    r.y = av.y / (1.f + __expf(-av.y)) * bv.y;
    r.z = av.z / (1.f + __expf(-av.z)) * bv.z;
    r.w = av.w / (1.f + __expf(-av.w)) * bv.w;
    __nv_bfloat162 h01 = __floats2bfloat162_rn(r.x, r.y);
    __nv_bfloat162 h23 = __floats2bfloat162_rn(r.z, r.w);
    float2 f01 = __bfloat1622float2(h01);
    float2 f23 = __bfloat1622float2(h23);
    __nv_bfloat162 l01 = __floats2bfloat162_rn(r.x - f01.x, r.y - f01.y);
    __nv_bfloat162 l23 = __floats2bfloat162_rn(r.z - f23.x, r.w - f23.y);
    hi[2*i] = h01; hi[2*i+1] = h23;
    lo[2*i] = l01; lo[2*i+1] = l23;
}

// ---------------- host-side launch helpers ----------------
static __nv_bfloat16 *s_whi, *s_wlo, *s_ahi, *s_alo, *s_bhi, *s_blo;

static void splitW(const float* W, uint32_t off, int K, int N) {
    split_t_kernel<<<dim3(N/32, K/32), dim3(32, 8)>>>(W, s_whi + off, s_wlo + off, K, N);
}
static void gemm(const __nv_bfloat16* ahi, const __nv_bfloat16* alo, uint32_t woff,
                 const float* R, float* Cf, __nv_bfloat16* chi, __nv_bfloat16* clo,
                 int M, int N, int K, int mode)
{
    dim3 grid(N / 128, M / 128);
    bgemm_kernel<<<grid, 256, BG_SMEM>>>(ahi, alo, s_whi + woff, s_wlo + woff,
                                         R, Cf, chi, clo, M, N, K, mode);
}

extern "C" void kernel_launch(void* const* d_in, const int* in_sizes, int n_in,
                              void* d_out, int out_size)
{
    const float* x    = (const float*)d_in[0];
    const float* enc  = (const float*)d_in[1];
    const float* Wq_s = (const float*)d_in[2];
    const float* Wk_s = (const float*)d_in[3];
    const float* Wv_s = (const float*)d_in[4];
    const float* Wo_s = (const float*)d_in[5];
    const float* lq1s = (const float*)d_in[6];
    const float* lk1s = (const float*)d_in[7];
    const float* lq2s = (const float*)d_in[8];
    const float* lk2s = (const float*)d_in[9];
    const float* Wq_c = (const float*)d_in[10];
    const float* Wk_c = (const float*)d_in[11];
    const float* Wv_c = (const float*)d_in[12];
    const float* Wo_c = (const float*)d_in[13];
    const float* lq1c = (const float*)d_in[14];
    const float* lk1c = (const float*)d_in[15];
    const float* lq2c = (const float*)d_in[16];
    const float* lk2c = (const float*)d_in[17];
    const float* grms = (const float*)d_in[18];
    const float* W1   = (const float*)d_in[19];
    const float* W2   = (const float*)d_in[20];
    const float* W3   = (const float*)d_in[21];
    float* out = (float*)d_out;

    float *hn, *q, *k, *v, *h2, *m1, *m2, *lam;
    cudaGetSymbolAddress((void**)&hn,  g_hn);
    cudaGetSymbolAddress((void**)&q,   g_q);
    cudaGetSymbolAddress((void**)&k,   g_k);
    cudaGetSymbolAddress((void**)&v,   g_v);
    cudaGetSymbolAddress((void**)&h2,  g_h2);
    cudaGetSymbolAddress((void**)&m1,  g_m1);
    cudaGetSymbolAddress((void**)&m2,  g_m2);
    cudaGetSymbolAddress((void**)&lam, g_lam);
    cudaGetSymbolAddress((void**)&s_whi, g_whi);
    cudaGetSymbolAddress((void**)&s_wlo, g_wlo);
    cudaGetSymbolAddress((void**)&s_ahi, g_ahi);
    cudaGetSymbolAddress((void**)&s_alo, g_alo);
    cudaGetSymbolAddress((void**)&s_bhi, g_bhi);
    cudaGetSymbolAddress((void**)&s_blo, g_blo);

    cudaFuncSetAttribute(flash_diff_kernel,
                         cudaFuncAttributeMaxDynamicSharedMemorySize, FL_SMEM);
    cudaFuncSetAttribute(bgemm_kernel,
                         cudaFuncAttributeMaxDynamicSharedMemorySize, BG_SMEM);

    // ---- weight split+transpose (bf16 hi/lo, [N][K]) ----
    splitW(Wq_s, OW_QS, 1024, 2048);
    splitW(Wk_s, OW_KS, 1024, 2048);
    splitW(Wv_s, OW_VS, 1024, 1024);
    splitW(Wo_s, OW_OS, 1024, 1024);
    splitW(Wq_c, OW_QC, 1024, 2048);
    splitW(Wk_c, OW_KC, 1024, 2048);
    splitW(Wv_c, OW_VC, 1024, 1024);
    splitW(Wo_c, OW_OC, 1024, 1024);
    splitW(W1,   OW_W1, 1024, 4096);
    splitW(W2,   OW_W2, 1024, 4096);
    splitW(W3,   OW_W3, 4096, 1024);

    // h = rmsnorm(x, g) -> fp32 hn (residual) + split in A
    rmsnorm_kernel<<<ROWS, 256>>>(x, grms, hn,
        (__nv_bfloat162*)s_ahi, (__nv_bfloat162*)s_alo);

    // ---- self diff-attention (causal) ----
    gemm(s_ahi, s_alo, OW_QS, nullptr, q, nullptr, nullptr, ROWS, 2048, 1024, 0);
    gemm(s_ahi, s_alo, OW_KS, nullptr, k, nullptr, nullptr, ROWS, 2048, 1024, 0);
    gemm(s_ahi, s_alo, OW_VS, nullptr, v, nullptr, nullptr, ROWS, 1024, 1024, 0);
    lambda_kernel<<<Hh, 32>>>(lq1s, lk1s, lq2s, lk2s, lam);
    flash_diff_kernel<<<dim3(Tt/64, Hh, Bb), 256, FL_SMEM>>>(q, k, v, lam,
        s_bhi, s_blo, Tt, Tt, 1);
    // h1 = ao @ Wo_s + hn  -> split only, into A
    gemm(s_bhi, s_blo, OW_OS, hn, nullptr, s_ahi, s_alo, ROWS, 1024, 1024, 1);

    // ---- cross diff-attention (not causal) ----
    gemm(s_ahi, s_alo, OW_QC, nullptr, q, nullptr, nullptr, ROWS, 2048, 1024, 0);
    split_kernel<<<(ROWS*1024/4)/256, 256>>>((const float4*)enc,
        (__nv_bfloat162*)s_bhi, (__nv_bfloat162*)s_blo, ROWS*1024/4);
    gemm(s_bhi, s_blo, OW_KC, nullptr, k, nullptr, nullptr, ROWS, 2048, 1024, 0);
    gemm(s_bhi, s_blo, OW_VC, nullptr, v, nullptr, nullptr, ROWS, 1024, 1024, 0);
    lambda_kernel<<<Hh, 32>>>(lq1c, lk1c, lq2c, lk2c, lam + 16);
    flash_diff_kernel<<<dim3(Tt/64, Hh, Bb), 256, FL_SMEM>>>(q, k, v, lam + 16,
        s_ahi, s_alo, Tt, Tt, 0);
    // h2 = 2 * (ao @ Wo_c) -> fp32 (residual + rmsnorm input)
    gemm(s_ahi, s_alo, OW_OC, nullptr, h2, nullptr, nullptr, ROWS, 1024, 1024, 2);

    // ---- MLP ----
    rmsnorm_kernel<<<ROWS, 256>>>(h2, grms, nullptr,
        (__nv_bfloat162*)s_ahi, (__nv_bfloat162*)s_alo);
    gemm(s_ahi, s_alo, OW_W1, nullptr, m1, nullptr, nullptr, ROWS, DFF, 1024, 0);
    gemm(s_ahi, s_alo, OW_W2, nullptr, m2, nullptr, nullptr, ROWS, DFF, 1024, 0);
    silu_mul_kernel<<<(ROWS*DFF/4)/256, 256>>>((const float4*)m1, (const float4*)m2,
        (__nv_bfloat162*)s_ahi, (__nv_bfloat162*)s_alo);
    gemm(s_ahi, s_alo, OW_W3, h2, out, nullptr, nullptr, ROWS, 1024, DFF, 1);
}

// round 9
// speedup vs baseline: 1.3132x; 1.3132x over previous
#include <cuda_runtime.h>
#include <cuda_bf16.h>
#include <math.h>
#include <stdint.h>

// ---------------- problem dims (fixed) ----------------
#define Bb   4
#define Tt   1024
#define Dd   1024
#define Hh   16
#define HSs  64
#define DFF  4096
#define ROWS (Bb*Tt)      // 4096

// ---------------- scratch (device globals; no allocs allowed) ----------------
__device__ float g_hn [ROWS*Dd];
__device__ float g_q  [ROWS*2048];
__device__ float g_k  [ROWS*2048];
__device__ float g_v  [ROWS*1024];
__device__ float g_h2 [ROWS*Dd];
__device__ float g_m1 [ROWS*DFF];
__device__ float g_m2 [ROWS*DFF];
__device__ float g_lam[32];

// bf16 hi/lo split buffers
#define NW_TOT (24u*1024u*1024u)
__device__ __nv_bfloat16 g_whi[NW_TOT];
__device__ __nv_bfloat16 g_wlo[NW_TOT];
#define NA_TOT (ROWS*DFF)
__device__ __nv_bfloat16 g_ahi[NA_TOT];
__device__ __nv_bfloat16 g_alo[NA_TOT];
#define NB_TOT (ROWS*1024)
__device__ __nv_bfloat16 g_bhi[NB_TOT];
__device__ __nv_bfloat16 g_blo[NB_TOT];

// weight offsets (elements)
#define OW_QS (0u)
#define OW_KS (2u*1024u*1024u)
#define OW_VS (4u*1024u*1024u)
#define OW_OS (5u*1024u*1024u)
#define OW_QC (6u*1024u*1024u)
#define OW_KC (8u*1024u*1024u)
#define OW_VC (10u*1024u*1024u)
#define OW_OC (11u*1024u*1024u)
#define OW_W1 (12u*1024u*1024u)
#define OW_W2 (16u*1024u*1024u)
#define OW_W3 (20u*1024u*1024u)

// ================= small helpers =================
__device__ __forceinline__ uint32_t smem_u32(const void* p) {
    uint32_t a;
    asm("{ .reg .u64 t; cvta.to.shared.u64 t, %1; cvt.u32.u64 %0, t; }" : "=r"(a) : "l"(p));
    return a;
}
__device__ __forceinline__ void cp16(uint32_t dst, const void* src) {
    asm volatile("cp.async.cg.shared.global [%0], [%1], 16;" :: "r"(dst), "l"(src) : "memory");
}
__device__ __forceinline__ void cp_commit() {
    asm volatile("cp.async.commit_group;" ::: "memory");
}
__device__ __forceinline__ void cp_wait2() {
    asm volatile("cp.async.wait_group 2;" ::: "memory");
}
__device__ __forceinline__ void mma16816(float* d, const uint32_t* a, const uint32_t* b) {
    asm volatile(
        "mma.sync.aligned.m16n8k16.row.col.f32.bf16.bf16.f32 "
        "{%0,%1,%2,%3}, {%4,%5,%6,%7}, {%8,%9}, {%0,%1,%2,%3};"
        : "+f"(d[0]), "+f"(d[1]), "+f"(d[2]), "+f"(d[3])
        : "r"(a[0]), "r"(a[1]), "r"(a[2]), "r"(a[3]), "r"(b[0]), "r"(b[1]));
}
__device__ __forceinline__ uint32_t lds32(uint32_t addr) {
    uint32_t v;
    asm volatile("ld.shared.b32 %0, [%1];" : "=r"(v) : "r"(addr));
    return v;
}

// ============ activation split: fp32 -> bf16 hi + bf16 lo ============
__global__ __launch_bounds__(256) void split_kernel(
    const float4* __restrict__ in, __nv_bfloat162* __restrict__ hi,
    __nv_bfloat162* __restrict__ lo, int n4)
{
    const int i = blockIdx.x * blockDim.x + threadIdx.x;
    if (i >= n4) return;
    float4 v = in[i];
    __nv_bfloat162 h01 = __floats2bfloat162_rn(v.x, v.y);
    __nv_bfloat162 h23 = __floats2bfloat162_rn(v.z, v.w);
    float2 f01 = __bfloat1622float2(h01);
    float2 f23 = __bfloat1622float2(h23);
    __nv_bfloat162 l01 = __floats2bfloat162_rn(v.x - f01.x, v.y - f01.y);
    __nv_bfloat162 l23 = __floats2bfloat162_rn(v.z - f23.x, v.w - f23.y);
    hi[2*i] = h01; hi[2*i+1] = h23;
    lo[2*i] = l01; lo[2*i+1] = l23;
}

// ============ weight split + transpose ============
__global__ __launch_bounds__(256) void split_t_kernel(
    const float* __restrict__ B, __nv_bfloat16* __restrict__ thi,
    __nv_bfloat16* __restrict__ tlo, int K, int N)
{
    __shared__ float tile[32][33];
    const int tx = threadIdx.x, ty = threadIdx.y;
    const int n0 = blockIdx.x * 32, k0 = blockIdx.y * 32;
#pragma unroll
    for (int j = ty; j < 32; j += 8)
        tile[j][tx] = B[(size_t)(k0 + j) * N + n0 + tx];
    __syncthreads();
#pragma unroll
    for (int j = ty; j < 32; j += 8) {
        float x = tile[tx][j];
        __nv_bfloat16 h = __float2bfloat16(x);
        __nv_bfloat16 l = __float2bfloat16(x - __bfloat162float(h));
        const size_t o = (size_t)(n0 + j) * K + k0 + tx;
        thi[o] = h; tlo[o] = l;
    }
}

// ============ bf16x3 tensor-core GEMM (proven mainloop) ============
#define BG_ROWB   80
#define BG_BUF    (128*BG_ROWB)
#define BG_STAGE  (4*BG_BUF)
#define BG_SMEM   (3*BG_STAGE)

__global__ __launch_bounds__(256) void bgemm_kernel(
    const __nv_bfloat16* __restrict__ Ahi, const __nv_bfloat16* __restrict__ Alo,
    const __nv_bfloat16* __restrict__ Bhi, const __nv_bfloat16* __restrict__ Blo,
    const float* __restrict__ R, float* __restrict__ Cf,
    __nv_bfloat16* __restrict__ Chi, __nv_bfloat16* __restrict__ Clo,
    int M, int N, int K, int mode)
{
    extern __shared__ char sm_c[];
    const uint32_t smb = smem_u32(sm_c);

    const int tid = threadIdx.x;
    const int wid = tid >> 5;
    const int lane = tid & 31;
    const int bm = blockIdx.y * 128, bn = blockIdx.x * 128;
    const int m0 = (wid >> 2) * 64;
    const int n0 = (wid & 3) * 32;
    const int qrow = lane >> 2;
    const int qk4 = (lane & 3) * 4;

    const int nch = K >> 5;

    auto issue_stage = [&](int t) {
        const int k0 = t * 32;
        const uint32_t sb = smb + (uint32_t)(t % 3) * BG_STAGE;
#pragma unroll
        for (int c = 0; c < 2; ++c) {
            const int idx = tid + c * 256;
            const int row = idx >> 2, q = idx & 3;
            const uint32_t so = (uint32_t)row * BG_ROWB + q * 16;
            const size_t goA = (size_t)(bm + row) * K + k0 + q * 8;
            const size_t goB = (size_t)(bn + row) * K + k0 + q * 8;
            cp16(sb + so,            Ahi + goA);
            cp16(sb + BG_BUF + so,   Alo + goA);
            cp16(sb + 2*BG_BUF + so, Bhi + goB);
            cp16(sb + 3*BG_BUF + so, Blo + goB);
        }
        cp_commit();
    };

    issue_stage(0); issue_stage(1); issue_stage(2);

    float acc[4][4][4];
#pragma unroll
    for (int a = 0; a < 4; ++a)
#pragma unroll
        for (int b = 0; b < 4; ++b)
#pragma unroll
            for (int c = 0; c < 4; ++c) acc[a][b][c] = 0.f;

    for (int t = 0; t < nch; ++t) {
        cp_wait2();
        __syncthreads();
        const char* Ah = sm_c + (t % 3) * BG_STAGE;
        const char* Al = Ah + BG_BUF;
        const char* Bh = Ah + 2*BG_BUF;
        const char* Bl = Ah + 3*BG_BUF;
#pragma unroll
        for (int kb = 0; kb <= 32; kb += 32) {
            uint32_t ahi[4][4], alo[4][4], bhi[4][2], blo[4][2];
#pragma unroll
            for (int mt = 0; mt < 4; ++mt) {
                const uint32_t off = (uint32_t)(m0 + mt*16 + qrow) * BG_ROWB + kb + qk4;
                ahi[mt][0] = *(const uint32_t*)(Ah + off);
                ahi[mt][1] = *(const uint32_t*)(Ah + off + 8*BG_ROWB);
                ahi[mt][2] = *(const uint32_t*)(Ah + off + 16);
                ahi[mt][3] = *(const uint32_t*)(Ah + off + 8*BG_ROWB + 16);
                alo[mt][0] = *(const uint32_t*)(Al + off);
                alo[mt][1] = *(const uint32_t*)(Al + off + 8*BG_ROWB);
                alo[mt][2] = *(const uint32_t*)(Al + off + 16);
                alo[mt][3] = *(const uint32_t*)(Al + off + 8*BG_ROWB + 16);
            }
#pragma unroll
            for (int nt = 0; nt < 4; ++nt) {
                const uint32_t off = (uint32_t)(n0 + nt*8 + qrow) * BG_ROWB + kb + qk4;
                bhi[nt][0] = *(const uint32_t*)(Bh + off);
                bhi[nt][1] = *(const uint32_t*)(Bh + off + 16);
                blo[nt][0] = *(const uint32_t*)(Bl + off);
                blo[nt][1] = *(const uint32_t*)(Bl + off + 16);
            }
#pragma unroll
            for (int mt = 0; mt < 4; ++mt)
#pragma unroll
                for (int nt = 0; nt < 4; ++nt) {
                    mma16816(acc[mt][nt], ahi[mt], bhi[nt]);
                    mma16816(acc[mt][nt], ahi[mt], blo[nt]);
                    mma16816(acc[mt][nt], alo[mt], bhi[nt]);
                }
        }
        __syncthreads();
        if (t + 3 < nch) issue_stage(t + 3);
        else cp_commit();
    }

#pragma unroll
    for (int mt = 0; mt < 4; ++mt) {
        const int r0 = bm + m0 + mt*16 + qrow;
#pragma unroll
        for (int nt = 0; nt < 4; ++nt) {
            const int c = bn + n0 + nt*8 + (lane & 3) * 2;
            float2 v0 = make_float2(acc[mt][nt][0], acc[mt][nt][1]);
            float2 v1 = make_float2(acc[mt][nt][2], acc[mt][nt][3]);
            if (mode == 1) {
                const float* q0 = R + (size_t)r0 * N + c;
                const float* q1 = R + (size_t)(r0 + 8) * N + c;
                v0.x += q0[0]; v0.y += q0[1];
                v1.x += q1[0]; v1.y += q1[1];
            } else if (mode == 2) {
                v0.x *= 2.f; v0.y *= 2.f; v1.x *= 2.f; v1.y *= 2.f;
            }
            if (Cf) {
                *(float2*)(Cf + (size_t)r0 * N + c) = v0;
                *(float2*)(Cf + (size_t)(r0 + 8) * N + c) = v1;
            }
            if (Chi) {
                __nv_bfloat162 h0 = __floats2bfloat162_rn(v0.x, v0.y);
                __nv_bfloat162 h1 = __floats2bfloat162_rn(v1.x, v1.y);
                float2 f0 = __bfloat1622float2(h0);
                float2 f1 = __bfloat1622float2(h1);
                __nv_bfloat162 l0 = __floats2bfloat162_rn(v0.x - f0.x, v0.y - f0.y);
                __nv_bfloat162 l1 = __floats2bfloat162_rn(v1.x - f1.x, v1.y - f1.y);
                *(__nv_bfloat162*)(Chi + (size_t)r0 * N + c) = h0;
                *(__nv_bfloat162*)(Chi + (size_t)(r0 + 8) * N + c) = h1;
                *(__nv_bfloat162*)(Clo + (size_t)r0 * N + c) = l0;
                *(__nv_bfloat162*)(Clo + (size_t)(r0 + 8) * N + c) = l1;
            }
        }
    }
}

// ---------------- rmsnorm: fp32 out (optional) + fused hi/lo split ----------------
__global__ __launch_bounds__(256) void rmsnorm_kernel(
    const float* __restrict__ x, const float* __restrict__ g,
    float* __restrict__ outf, __nv_bfloat162* __restrict__ hi,
    __nv_bfloat162* __restrict__ lo)
{
    __shared__ float red[8];
    __shared__ float sscale;
    const int row = blockIdx.x;
    const int t = threadIdx.x;
    const float4* xr = (const float4*)(x + (size_t)row * 1024);
    float4 v = xr[t];
    float ss = v.x*v.x + v.y*v.y + v.z*v.z + v.w*v.w;
#pragma unroll
    for (int o = 16; o; o >>= 1) ss += __shfl_xor_sync(0xffffffffu, ss, o);
    if ((t & 31) == 0) red[t >> 5] = ss;
    __syncthreads();
    if (t == 0) {
        float s = 0.f;
#pragma unroll
        for (int i = 0; i < 8; ++i) s += red[i];
        sscale = rsqrtf(s * (1.0f/1024.0f) + 1e-6f);
    }
    __syncthreads();
    const float sc = sscale;
    float4 gv = ((const float4*)g)[t];
    float4 o;
    o.x = v.x*sc*gv.x; o.y = v.y*sc*gv.y; o.z = v.z*sc*gv.z; o.w = v.w*sc*gv.w;
    if (outf) ((float4*)(outf + (size_t)row * 1024))[t] = o;
    __nv_bfloat162 h01 = __floats2bfloat162_rn(o.x, o.y);
    __nv_bfloat162 h23 = __floats2bfloat162_rn(o.z, o.w);
    float2 f01 = __bfloat1622float2(h01);
    float2 f23 = __bfloat1622float2(h23);
    __nv_bfloat162 l01 = __floats2bfloat162_rn(o.x - f01.x, o.y - f01.y);
    __nv_bfloat162 l23 = __floats2bfloat162_rn(o.z - f23.x, o.w - f23.y);
    const size_t p = (size_t)row * 512 + t * 2;
    hi[p] = h01; hi[p+1] = h23;
    lo[p] = l01; lo[p+1] = l23;
}

// ---------------- lambda ----------------
__global__ void lambda_kernel(const float* __restrict__ lq1, const float* __restrict__ lk1,
                              const float* __restrict__ lq2, const float* __restrict__ lk2,
                              float* __restrict__ lam)
{
    const int h = blockIdx.x;
    const int lane = threadIdx.x;
    float s1 = 0.f, s2 = 0.f;
    for (int d = lane; d < 64; d += 32) {
        s1 += lq1[h*64 + d] * lk1[h*64 + d];
        s2 += lq2[h*64 + d] * lk2[h*64 + d];
    }
#pragma unroll
    for (int o = 16; o; o >>= 1) {
        s1 += __shfl_xor_sync(0xffffffffu, s1, o);
        s2 += __shfl_xor_sync(0xffffffffu, s2, o);
    }
    if (lane == 0) lam[h] = expf(s1) - expf(s2) + 0.8f;
}

// ================ tensor-core flash diff-attention (bf16x3) ================
// smem layout (bytes): rows padded to 144B (64 bf16 + 16B pad)
#define FLM_ROWB 144u
#define SQ1H 0u
#define SQ1L 9216u
#define SQ2H 18432u
#define SQ2L 27648u
#define SK1H 36864u
#define SK1L 46080u
#define SK2H 55296u
#define SK2L 64512u
#define SVH  73728u
#define SVL  82944u
#define FLM_SMEM 92160
#define SOEX 36864u          // fp32 exchange buffer (reuses K region), 64 x 68 floats

__global__ __launch_bounds__(256, 2) void flash_mma_kernel(
    const float* __restrict__ Q, const float* __restrict__ Kg,
    const float* __restrict__ Vg, const float* __restrict__ lamp,
    __nv_bfloat16* __restrict__ Ohi, __nv_bfloat16* __restrict__ Olo,
    int Sq, int Sk, int causal)
{
    extern __shared__ char smf[];
    const uint32_t smb = smem_u32(smf);
    const int tid = threadIdx.x, wid = tid >> 5, lane = tid & 31;
    const int g = lane >> 2, qq = lane & 3;
    const int qt = blockIdx.x, h = blockIdx.y, b = blockIdx.z;
    const int mat = wid >> 2;            // 0: softmax1 warps, 1: softmax2 warps
    const int slab = (wid & 3) * 16;

    // ---- load Q (both components), split to bf16 hi/lo in smem ----
#pragma unroll
    for (int u = 0; u < 8; ++u) {
        const int idx = tid + u * 256;
        const int r = idx >> 5, d0 = (idx & 31) * 4;
        const float4 v = *(const float4*)(Q + ((size_t)(b*Sq + qt*64 + r) * Hh + h) * 128 + d0);
        const uint32_t off = ((d0 < 64) ? SQ1H : SQ2H) + (uint32_t)r * FLM_ROWB + (uint32_t)(d0 & 63) * 2;
        __nv_bfloat162 h01 = __floats2bfloat162_rn(v.x, v.y);
        __nv_bfloat162 h23 = __floats2bfloat162_rn(v.z, v.w);
        float2 f01 = __bfloat1622float2(h01), f23 = __bfloat1622float2(h23);
        __nv_bfloat162 l01 = __floats2bfloat162_rn(v.x - f01.x, v.y - f01.y);
        __nv_bfloat162 l23 = __floats2bfloat162_rn(v.z - f23.x, v.w - f23.y);
        *(__nv_bfloat162*)(smf + off)        = h01;
        *(__nv_bfloat162*)(smf + off + 4)    = h23;
        *(__nv_bfloat162*)(smf + off + 9216) = l01;
        *(__nv_bfloat162*)(smf + off + 9220) = l23;
    }

    float O[8][4];
#pragma unroll
    for (int t = 0; t < 8; ++t)
#pragma unroll
        for (int c = 0; c < 4; ++c) O[t][c] = 0.f;
    float rm[2] = { -1e30f, -1e30f }, rl[2] = { 0.f, 0.f };

    const int nkt = causal ? (qt + 1) : (Sk >> 6);

    for (int kt = 0; kt < nkt; ++kt) {
        __syncthreads();   // prior PV reads of Vt + prior score reads of K done
        // ---- load K (both comps) + V, split ----
#pragma unroll
        for (int u = 0; u < 8; ++u) {
            const int idx = tid + u * 256;
            const int r = idx >> 5, d0 = (idx & 31) * 4;
            const float4 v = *(const float4*)(Kg + ((size_t)(b*Sk + kt*64 + r) * Hh + h) * 128 + d0);
            const uint32_t off = ((d0 < 64) ? SK1H : SK2H) + (uint32_t)r * FLM_ROWB + (uint32_t)(d0 & 63) * 2;
            __nv_bfloat162 h01 = __floats2bfloat162_rn(v.x, v.y);
            __nv_bfloat162 h23 = __floats2bfloat162_rn(v.z, v.w);
            float2 f01 = __bfloat1622float2(h01), f23 = __bfloat1622float2(h23);
            __nv_bfloat162 l01 = __floats2bfloat162_rn(v.x - f01.x, v.y - f01.y);
            __nv_bfloat162 l23 = __floats2bfloat162_rn(v.z - f23.x, v.w - f23.y);
            *(__nv_bfloat162*)(smf + off)        = h01;
            *(__nv_bfloat162*)(smf + off + 4)    = h23;
            *(__nv_bfloat162*)(smf + off + 9216) = l01;
            *(__nv_bfloat162*)(smf + off + 9220) = l23;
        }
#pragma unroll
        for (int u = 0; u < 4; ++u) {
            const int idx = tid + u * 256;
            const int key = idx >> 4, d0 = (idx & 15) * 4;
            const float4 v = *(const float4*)(Vg + ((size_t)(b*Sk + kt*64 + key) * Hh + h) * 64 + d0);
            const float vv[4] = { v.x, v.y, v.z, v.w };
#pragma unroll
            for (int j = 0; j < 4; ++j) {
                const float f = vv[j];
                __nv_bfloat16 hb = __float2bfloat16(f);
                __nv_bfloat16 lb = __float2bfloat16(f - __bfloat162float(hb));
                const uint32_t o2 = (uint32_t)(d0 + j) * FLM_ROWB + (uint32_t)key * 2;
                *(__nv_bfloat16*)(smf + SVH + o2) = hb;
                *(__nv_bfloat16*)(smf + SVL + o2) = lb;
            }
        }
        __syncthreads();

        // ---- scores S = Q K^T (bf16x3, fp32 acc) ----
        float S[8][4];
#pragma unroll
        for (int t = 0; t < 8; ++t)
#pragma unroll
            for (int c = 0; c < 4; ++c) S[t][c] = 0.f;

        const uint32_t qB = smb + (mat ? SQ2H : SQ1H);
        const uint32_t kB = smb + (mat ? SK2H : SK1H);
#pragma unroll
        for (int s = 0; s < 4; ++s) {
            uint32_t ah[4], al[4];
            const uint32_t ao = qB + (uint32_t)(slab + g) * FLM_ROWB + s * 32 + qq * 4;
            ah[0] = lds32(ao);              ah[1] = lds32(ao + 8*FLM_ROWB);
            ah[2] = lds32(ao + 16);         ah[3] = lds32(ao + 8*FLM_ROWB + 16);
            al[0] = lds32(ao + 9216);       al[1] = lds32(ao + 9216 + 8*FLM_ROWB);
            al[2] = lds32(ao + 9216 + 16);  al[3] = lds32(ao + 9216 + 8*FLM_ROWB + 16);
#pragma unroll
            for (int nt = 0; nt < 8; ++nt) {
                const uint32_t bo = kB + (uint32_t)(nt*8 + g) * FLM_ROWB + s * 32 + qq * 4;
                uint32_t bh[2], bl[2];
                bh[0] = lds32(bo);        bh[1] = lds32(bo + 16);
                bl[0] = lds32(bo + 9216); bl[1] = lds32(bo + 9216 + 16);
                mma16816(S[nt], ah, bh);
                mma16816(S[nt], ah, bl);
                mma16816(S[nt], al, bh);
            }
        }

        // ---- online softmax (per warp, rows slab+g and slab+g+8) ----
        const bool dg = (causal != 0) && (kt == qt);
        uint32_t pH[8][2], pL[8][2];
#pragma unroll
        for (int j = 0; j < 2; ++j) {
            const int rloc = slab + g + j*8;
            float mx = -1e30f;
#pragma unroll
            for (int t = 0; t < 8; ++t) {
                float* sp = &S[t][j*2];
                sp[0] *= 0.125f; sp[1] *= 0.125f;
                if (dg) {
                    const int c = t*8 + qq*2;
                    if (c > rloc)     sp[0] = -1e9f;
                    if (c + 1 > rloc) sp[1] = -1e9f;
                }
                mx = fmaxf(mx, fmaxf(sp[0], sp[1]));
            }
            mx = fmaxf(mx, __shfl_xor_sync(0xffffffffu, mx, 1));
            mx = fmaxf(mx, __shfl_xor_sync(0xffffffffu, mx, 2));
            const float mn = fmaxf(rm[j], mx);
            const float alw = __expf(rm[j] - mn);
            rm[j] = mn;
            float rs = 0.f;
#pragma unroll
            for (int t = 0; t < 8; ++t) {
                const float p0 = __expf(S[t][j*2]   - mn);
                const float p1 = __expf(S[t][j*2+1] - mn);
                rs += p0 + p1;
                __nv_bfloat162 hp = __floats2bfloat162_rn(p0, p1);
                float2 fp = __bfloat1622float2(hp);
                __nv_bfloat162 lp = __floats2bfloat162_rn(p0 - fp.x, p1 - fp.y);
                pH[t][j] = *(uint32_t*)&hp;
                pL[t][j] = *(uint32_t*)&lp;
            }
            rs += __shfl_xor_sync(0xffffffffu, rs, 1);
            rs += __shfl_xor_sync(0xffffffffu, rs, 2);
            rl[j] = rl[j] * alw + rs;
#pragma unroll
            for (int t = 0; t < 8; ++t) { O[t][j*2] *= alw; O[t][j*2+1] *= alw; }
        }

        // ---- O += P V (bf16x3; P from registers, V^T from smem) ----
#pragma unroll
        for (int s = 0; s < 4; ++s) {
            const uint32_t aP[4]  = { pH[2*s][0], pH[2*s][1], pH[2*s+1][0], pH[2*s+1][1] };
            const uint32_t aPl[4] = { pL[2*s][0], pL[2*s][1], pL[2*s+1][0], pL[2*s+1][1] };
#pragma unroll
            for (int nt = 0; nt < 8; ++nt) {
                const uint32_t bo = smb + SVH + (uint32_t)(nt*8 + g) * FLM_ROWB + s * 32 + qq * 4;
                uint32_t bh[2], bl[2];
                bh[0] = lds32(bo);        bh[1] = lds32(bo + 16);
                bl[0] = lds32(bo + 9216); bl[1] = lds32(bo + 9216 + 16);
                mma16816(O[nt], aP,  bh);
                mma16816(O[nt], aP,  bl);
                mma16816(O[nt], aPl, bh);
            }
        }
    }

    __syncthreads();   // all score reads of K done before SOEX overwrite
    if (mat == 1) {
#pragma unroll
        for (int j = 0; j < 2; ++j) {
            const float inv = 1.f / rl[j];
            const int row = slab + g + j*8;
#pragma unroll
            for (int t = 0; t < 8; ++t) {
                const int col = t*8 + qq*2;
                float2 w = make_float2(O[t][j*2] * inv, O[t][j*2+1] * inv);
                *(float2*)(smf + SOEX + ((uint32_t)row * 68 + col) * 4) = w;
            }
        }
    }
    __syncthreads();
    if (mat == 0) {
        const float lam = lamp[h];
#pragma unroll
        for (int j = 0; j < 2; ++j) {
            const float inv = 1.f / rl[j];
            const int row = slab + g + j*8;
            float vbuf[16];
            float ss = 0.f;
#pragma unroll
            for (int t = 0; t < 8; ++t) {
                const int col = t*8 + qq*2;
                const float2 w = *(const float2*)(smf + SOEX + ((uint32_t)row * 68 + col) * 4);
                const float v0 = O[t][j*2]   * inv - lam * w.x;
                const float v1 = O[t][j*2+1] * inv - lam * w.y;
                vbuf[2*t] = v0; vbuf[2*t+1] = v1;
                ss += v0*v0 + v1*v1;
            }
            ss += __shfl_xor_sync(0xffffffffu, ss, 1);
            ss += __shfl_xor_sync(0xffffffffu, ss, 2);
            const float scl = rsqrtf(ss * (1.0f/64.0f) + 1e-6f) * 0.2f;
            const size_t ob = ((size_t)(b*Sq + qt*64 + row) * Hh + h) * 64;
#pragma unroll
            for (int t = 0; t < 8; ++t) {
                const int col = t*8 + qq*2;
                const float v0 = vbuf[2*t] * scl, v1 = vbuf[2*t+1] * scl;
                __nv_bfloat162 hh = __floats2bfloat162_rn(v0, v1);
                float2 fh = __bfloat1622float2(hh);
                __nv_bfloat162 ll = __floats2bfloat162_rn(v0 - fh.x, v1 - fh.y);
                *(__nv_bfloat162*)(Ohi + ob + col) = hh;
                *(__nv_bfloat162*)(Olo + ob + col) = ll;
            }
        }
    }
}

// ---------------- silu(a) * b with fused hi/lo split ----------------
__global__ void silu_mul_kernel(const float4* __restrict__ a, const float4* __restrict__ b,
                                __nv_bfloat162* __restrict__ hi, __nv_bfloat162* __restrict__ lo)
{
    const int i = blockIdx.x * blockDim.x + threadIdx.x;
    float4 av = a[i], bv = b[i], r;
    r.x = av.x / (1.f + __expf(-av.x)) * bv.x;
    r.y = av.y / (1.f + __expf(-av.y)) * bv.y;
    r.z = av.z / (1.f + __expf(-av.z)) * bv.z;
    r.w = av.w / (1.f + __expf(-av.w)) * bv.w;
    __nv_bfloat162 h01 = __floats2bfloat162_rn(r.x, r.y);
    __nv_bfloat162 h23 = __floats2bfloat162_rn(r.z, r.w);
    float2 f01 = __bfloat1622float2(h01);
    float2 f23 = __bfloat1622float2(h23);
    __nv_bfloat162 l01 = __floats2bfloat162_rn(r.x - f01.x, r.y - f01.y);
    __nv_bfloat162 l23 = __floats2bfloat162_rn(r.z - f23.x, r.w - f23.y);
    hi[2*i] = h01; hi[2*i+1] = h23;
    lo[2*i] = l01; lo[2*i+1] = l23;
}

// ---------------- host-side launch helpers ----------------
static __nv_bfloat16 *s_whi, *s_wlo, *s_ahi, *s_alo, *s_bhi, *s_blo;

static void splitW(const float* W, uint32_t off, int K, int N) {
    split_t_kernel<<<dim3(N/32, K/32), dim3(32, 8)>>>(W, s_whi + off, s_wlo + off, K, N);
}
static void gemm(const __nv_bfloat16* ahi, const __nv_bfloat16* alo, uint32_t woff,
                 const float* R, float* Cf, __nv_bfloat16* chi, __nv_bfloat16* clo,
                 int M, int N, int K, int mode)
{
    dim3 grid(N / 128, M / 128);
    bgemm_kernel<<<grid, 256, BG_SMEM>>>(ahi, alo, s_whi + woff, s_wlo + woff,
                                         R, Cf, chi, clo, M, N, K, mode);
}

extern "C" void kernel_launch(void* const* d_in, const int* in_sizes, int n_in,
                              void* d_out, int out_size)
{
    const float* x    = (const float*)d_in[0];
    const float* enc  = (const float*)d_in[1];
    const float* Wq_s = (const float*)d_in[2];
    const float* Wk_s = (const float*)d_in[3];
    const float* Wv_s = (const float*)d_in[4];
    const float* Wo_s = (const float*)d_in[5];
    const float* lq1s = (const float*)d_in[6];
    const float* lk1s = (const float*)d_in[7];
    const float* lq2s = (const float*)d_in[8];
    const float* lk2s = (const float*)d_in[9];
    const float* Wq_c = (const float*)d_in[10];
    const float* Wk_c = (const float*)d_in[11];
    const float* Wv_c = (const float*)d_in[12];
    const float* Wo_c = (const float*)d_in[13];
    const float* lq1c = (const float*)d_in[14];
    const float* lk1c = (const float*)d_in[15];
    const float* lq2c = (const float*)d_in[16];
    const float* lk2c = (const float*)d_in[17];
    const float* grms = (const float*)d_in[18];
    const float* W1   = (const float*)d_in[19];
    const float* W2   = (const float*)d_in[20];
    const float* W3   = (const float*)d_in[21];
    float* out = (float*)d_out;

    float *hn, *q, *k, *v, *h2, *m1, *m2, *lam;
    cudaGetSymbolAddress((void**)&hn,  g_hn);
    cudaGetSymbolAddress((void**)&q,   g_q);
    cudaGetSymbolAddress((void**)&k,   g_k);
    cudaGetSymbolAddress((void**)&v,   g_v);
    cudaGetSymbolAddress((void**)&h2,  g_h2);
    cudaGetSymbolAddress((void**)&m1,  g_m1);
    cudaGetSymbolAddress((void**)&m2,  g_m2);
    cudaGetSymbolAddress((void**)&lam, g_lam);
    cudaGetSymbolAddress((void**)&s_whi, g_whi);
    cudaGetSymbolAddress((void**)&s_wlo, g_wlo);
    cudaGetSymbolAddress((void**)&s_ahi, g_ahi);
    cudaGetSymbolAddress((void**)&s_alo, g_alo);
    cudaGetSymbolAddress((void**)&s_bhi, g_bhi);
    cudaGetSymbolAddress((void**)&s_blo, g_blo);

    cudaFuncSetAttribute(flash_mma_kernel,
                         cudaFuncAttributeMaxDynamicSharedMemorySize, FLM_SMEM);
    cudaFuncSetAttribute(bgemm_kernel,
                         cudaFuncAttributeMaxDynamicSharedMemorySize, BG_SMEM);

    // ---- weight split+transpose (bf16 hi/lo, [N][K]) ----
    splitW(Wq_s, OW_QS, 1024, 2048);
    splitW(Wk_s, OW_KS, 1024, 2048);
    splitW(Wv_s, OW_VS, 1024, 1024);
    splitW(Wo_s, OW_OS, 1024, 1024);
    splitW(Wq_c, OW_QC, 1024, 2048);
    splitW(Wk_c, OW_KC, 1024, 2048);
    splitW(Wv_c, OW_VC, 1024, 1024);
    splitW(Wo_c, OW_OC, 1024, 1024);
    splitW(W1,   OW_W1, 1024, 4096);
    splitW(W2,   OW_W2, 1024, 4096);
    splitW(W3,   OW_W3, 4096, 1024);

    // h = rmsnorm(x, g) -> fp32 hn (residual) + split in A
    rmsnorm_kernel<<<ROWS, 256>>>(x, grms, hn,
        (__nv_bfloat162*)s_ahi, (__nv_bfloat162*)s_alo);

    // ---- self diff-attention (causal) ----
    gemm(s_ahi, s_alo, OW_QS, nullptr, q, nullptr, nullptr, ROWS, 2048, 1024, 0);
    gemm(s_ahi, s_alo, OW_KS, nullptr, k, nullptr, nullptr, ROWS, 2048, 1024, 0);
    gemm(s_ahi, s_alo, OW_VS, nullptr, v, nullptr, nullptr, ROWS, 1024, 1024, 0);
    lambda_kernel<<<Hh, 32>>>(lq1s, lk1s, lq2s, lk2s, lam);
    flash_mma_kernel<<<dim3(Tt/64, Hh, Bb), 256, FLM_SMEM>>>(q, k, v, lam,
        s_bhi, s_blo, Tt, Tt, 1);
    // h1 = ao @ Wo_s + hn  -> split only, into A
    gemm(s_bhi, s_blo, OW_OS, hn, nullptr, s_ahi, s_alo, ROWS, 1024, 1024, 1);

    // ---- cross diff-attention (not causal) ----
    gemm(s_ahi, s_alo, OW_QC, nullptr, q, nullptr, nullptr, ROWS, 2048, 1024, 0);
    split_kernel<<<(ROWS*1024/4)/256, 256>>>((const float4*)enc,
        (__nv_bfloat162*)s_bhi, (__nv_bfloat162*)s_blo, ROWS*1024/4);
    gemm(s_bhi, s_blo, OW_KC, nullptr, k, nullptr, nullptr, ROWS, 2048, 1024, 0);
    gemm(s_bhi, s_blo, OW_VC, nullptr, v, nullptr, nullptr, ROWS, 1024, 1024, 0);
    lambda_kernel<<<Hh, 32>>>(lq1c, lk1c, lq2c, lk2c, lam + 16);
    flash_mma_kernel<<<dim3(Tt/64, Hh, Bb), 256, FLM_SMEM>>>(q, k, v, lam + 16,
        s_ahi, s_alo, Tt, Tt, 0);
    // h2 = 2 * (ao @ Wo_c) -> fp32 (residual + rmsnorm input)
    gemm(s_ahi, s_alo, OW_OC, nullptr, h2, nullptr, nullptr, ROWS, 1024, 1024, 2);

    // ---- MLP ----
    rmsnorm_kernel<<<ROWS, 256>>>(h2, grms, nullptr,
        (__nv_bfloat162*)s_ahi, (__nv_bfloat162*)s_alo);
    gemm(s_ahi, s_alo, OW_W1, nullptr, m1, nullptr, nullptr, ROWS, DFF, 1024, 0);
    gemm(s_ahi, s_alo, OW_W2, nullptr, m2, nullptr, nullptr, ROWS, DFF, 1024, 0);
    silu_mul_kernel<<<(ROWS*DFF/4)/256, 256>>>((const float4*)m1, (const float4*)m2,
        (__nv_bfloat162*)s_ahi, (__nv_bfloat162*)s_alo);
    gemm(s_ahi, s_alo, OW_W3, h2, out, nullptr, nullptr, ROWS, 1024, DFF, 1);
}

// round 10
// speedup vs baseline: 1.4897x; 1.1344x over previous
#include <cuda_runtime.h>
#include <cuda_bf16.h>
#include <cuda_fp16.h>
#include <math.h>
#include <stdint.h>

// ---------------- problem dims (fixed) ----------------
#define Bb   4
#define Tt   1024
#define Dd   1024
#define Hh   16
#define HSs  64
#define DFF  4096
#define ROWS (Bb*Tt)      // 4096

// ---------------- scratch (device globals; no allocs allowed) ----------------
__device__ float g_hn [ROWS*Dd];
__device__ float g_q  [ROWS*2048];
__device__ float g_k  [ROWS*2048];
__device__ float g_v  [ROWS*1024];
__device__ float g_h2 [ROWS*Dd];
__device__ float g_m1 [ROWS*DFF];
__device__ float g_lam[32];

// bf16 hi/lo split buffers (attention path)
#define NW_TOT (24u*1024u*1024u)
__device__ __nv_bfloat16 g_whi[NW_TOT];
__device__ __nv_bfloat16 g_wlo[NW_TOT];
#define NA_TOT (ROWS*DFF)
__device__ __nv_bfloat16 g_ahi[NA_TOT];
__device__ __nv_bfloat16 g_alo[NA_TOT];
#define NB_TOT (ROWS*DFF)
__device__ __nv_bfloat16 g_bhi[NB_TOT];
__device__ __nv_bfloat16 g_blo[NB_TOT];

// fp16 weights for MLP path (single precision term)
#define NHW_TOT (12u*1024u*1024u)
__device__ __half g_wh[NHW_TOT];
#define OHW1 (0u)
#define OHW2 (4u*1024u*1024u)
#define OHW3 (8u*1024u*1024u)

// bf16 weight offsets (elements)
#define OW_QS (0u)
#define OW_KS (2u*1024u*1024u)
#define OW_VS (4u*1024u*1024u)
#define OW_OS (5u*1024u*1024u)
#define OW_QC (6u*1024u*1024u)
#define OW_KC (8u*1024u*1024u)
#define OW_VC (10u*1024u*1024u)
#define OW_OC (11u*1024u*1024u)

// ================= small helpers =================
__device__ __forceinline__ uint32_t smem_u32(const void* p) {
    uint32_t a;
    asm("{ .reg .u64 t; cvta.to.shared.u64 t, %1; cvt.u32.u64 %0, t; }" : "=r"(a) : "l"(p));
    return a;
}
__device__ __forceinline__ void cp16(uint32_t dst, const void* src) {
    asm volatile("cp.async.cg.shared.global [%0], [%1], 16;" :: "r"(dst), "l"(src) : "memory");
}
__device__ __forceinline__ void cp_commit() {
    asm volatile("cp.async.commit_group;" ::: "memory");
}
__device__ __forceinline__ void cp_wait2() {
    asm volatile("cp.async.wait_group 2;" ::: "memory");
}
__device__ __forceinline__ void mma16816(float* d, const uint32_t* a, const uint32_t* b) {
    asm volatile(
        "mma.sync.aligned.m16n8k16.row.col.f32.bf16.bf16.f32 "
        "{%0,%1,%2,%3}, {%4,%5,%6,%7}, {%8,%9}, {%0,%1,%2,%3};"
        : "+f"(d[0]), "+f"(d[1]), "+f"(d[2]), "+f"(d[3])
        : "r"(a[0]), "r"(a[1]), "r"(a[2]), "r"(a[3]), "r"(b[0]), "r"(b[1]));
}
__device__ __forceinline__ void mma16816h(float* d, const uint32_t* a, const uint32_t* b) {
    asm volatile(
        "mma.sync.aligned.m16n8k16.row.col.f32.f16.f16.f32 "
        "{%0,%1,%2,%3}, {%4,%5,%6,%7}, {%8,%9}, {%0,%1,%2,%3};"
        : "+f"(d[0]), "+f"(d[1]), "+f"(d[2]), "+f"(d[3])
        : "r"(a[0]), "r"(a[1]), "r"(a[2]), "r"(a[3]), "r"(b[0]), "r"(b[1]));
}
__device__ __forceinline__ uint32_t lds32(uint32_t addr) {
    uint32_t v;
    asm volatile("ld.shared.b32 %0, [%1];" : "=r"(v) : "r"(addr));
    return v;
}

// ============ activation split: fp32 -> bf16 hi + bf16 lo ============
__global__ __launch_bounds__(256) void split_kernel(
    const float4* __restrict__ in, __nv_bfloat162* __restrict__ hi,
    __nv_bfloat162* __restrict__ lo, int n4)
{
    const int i = blockIdx.x * blockDim.x + threadIdx.x;
    if (i >= n4) return;
    float4 v = in[i];
    __nv_bfloat162 h01 = __floats2bfloat162_rn(v.x, v.y);
    __nv_bfloat162 h23 = __floats2bfloat162_rn(v.z, v.w);
    float2 f01 = __bfloat1622float2(h01);
    float2 f23 = __bfloat1622float2(h23);
    __nv_bfloat162 l01 = __floats2bfloat162_rn(v.x - f01.x, v.y - f01.y);
    __nv_bfloat162 l23 = __floats2bfloat162_rn(v.z - f23.x, v.w - f23.y);
    hi[2*i] = h01; hi[2*i+1] = h23;
    lo[2*i] = l01; lo[2*i+1] = l23;
}

// ============ weight split + transpose: bf16 hi/lo ============
__global__ __launch_bounds__(256) void split_t_kernel(
    const float* __restrict__ B, __nv_bfloat16* __restrict__ thi,
    __nv_bfloat16* __restrict__ tlo, int K, int N)
{
    __shared__ float tile[32][33];
    const int tx = threadIdx.x, ty = threadIdx.y;
    const int n0 = blockIdx.x * 32, k0 = blockIdx.y * 32;
#pragma unroll
    for (int j = ty; j < 32; j += 8)
        tile[j][tx] = B[(size_t)(k0 + j) * N + n0 + tx];
    __syncthreads();
#pragma unroll
    for (int j = ty; j < 32; j += 8) {
        float x = tile[tx][j];
        __nv_bfloat16 h = __float2bfloat16(x);
        __nv_bfloat16 l = __float2bfloat16(x - __bfloat162float(h));
        const size_t o = (size_t)(n0 + j) * K + k0 + tx;
        thi[o] = h; tlo[o] = l;
    }
}

// ============ weight transpose: single fp16 (MLP) ============
__global__ __launch_bounds__(256) void split_t_h_kernel(
    const float* __restrict__ B, __half* __restrict__ th, int K, int N)
{
    __shared__ float tile[32][33];
    const int tx = threadIdx.x, ty = threadIdx.y;
    const int n0 = blockIdx.x * 32, k0 = blockIdx.y * 32;
#pragma unroll
    for (int j = ty; j < 32; j += 8)
        tile[j][tx] = B[(size_t)(k0 + j) * N + n0 + tx];
    __syncthreads();
#pragma unroll
    for (int j = ty; j < 32; j += 8) {
        const size_t o = (size_t)(n0 + j) * K + k0 + tx;
        th[o] = __float2half(tile[tx][j]);
    }
}

// ============ bf16x3 tensor-core GEMM (proven mainloop) ============
#define BG_ROWB   80
#define BG_BUF    (128*BG_ROWB)
#define BG_STAGE  (4*BG_BUF)
#define BG_SMEM   (3*BG_STAGE)

__global__ __launch_bounds__(256) void bgemm_kernel(
    const __nv_bfloat16* __restrict__ Ahi, const __nv_bfloat16* __restrict__ Alo,
    const __nv_bfloat16* __restrict__ Bhi, const __nv_bfloat16* __restrict__ Blo,
    const float* __restrict__ R, float* __restrict__ Cf,
    __nv_bfloat16* __restrict__ Chi, __nv_bfloat16* __restrict__ Clo,
    int M, int N, int K, int mode)
{
    extern __shared__ char sm_c[];
    const uint32_t smb = smem_u32(sm_c);

    const int tid = threadIdx.x;
    const int wid = tid >> 5;
    const int lane = tid & 31;
    const int bm = blockIdx.y * 128, bn = blockIdx.x * 128;
    const int m0 = (wid >> 2) * 64;
    const int n0 = (wid & 3) * 32;
    const int qrow = lane >> 2;
    const int qk4 = (lane & 3) * 4;

    const int nch = K >> 5;

    auto issue_stage = [&](int t) {
        const int k0 = t * 32;
        const uint32_t sb = smb + (uint32_t)(t % 3) * BG_STAGE;
#pragma unroll
        for (int c = 0; c < 2; ++c) {
            const int idx = tid + c * 256;
            const int row = idx >> 2, q = idx & 3;
            const uint32_t so = (uint32_t)row * BG_ROWB + q * 16;
            const size_t goA = (size_t)(bm + row) * K + k0 + q * 8;
            const size_t goB = (size_t)(bn + row) * K + k0 + q * 8;
            cp16(sb + so,            Ahi + goA);
            cp16(sb + BG_BUF + so,   Alo + goA);
            cp16(sb + 2*BG_BUF + so, Bhi + goB);
            cp16(sb + 3*BG_BUF + so, Blo + goB);
        }
        cp_commit();
    };

    issue_stage(0); issue_stage(1); issue_stage(2);

    float acc[4][4][4];
#pragma unroll
    for (int a = 0; a < 4; ++a)
#pragma unroll
        for (int b = 0; b < 4; ++b)
#pragma unroll
            for (int c = 0; c < 4; ++c) acc[a][b][c] = 0.f;

    for (int t = 0; t < nch; ++t) {
        cp_wait2();
        __syncthreads();
        const char* Ah = sm_c + (t % 3) * BG_STAGE;
        const char* Al = Ah + BG_BUF;
        const char* Bh = Ah + 2*BG_BUF;
        const char* Bl = Ah + 3*BG_BUF;
#pragma unroll
        for (int kb = 0; kb <= 32; kb += 32) {
            uint32_t ahi[4][4], alo[4][4], bhi[4][2], blo[4][2];
#pragma unroll
            for (int mt = 0; mt < 4; ++mt) {
                const uint32_t off = (uint32_t)(m0 + mt*16 + qrow) * BG_ROWB + kb + qk4;
                ahi[mt][0] = *(const uint32_t*)(Ah + off);
                ahi[mt][1] = *(const uint32_t*)(Ah + off + 8*BG_ROWB);
                ahi[mt][2] = *(const uint32_t*)(Ah + off + 16);
                ahi[mt][3] = *(const uint32_t*)(Ah + off + 8*BG_ROWB + 16);
                alo[mt][0] = *(const uint32_t*)(Al + off);
                alo[mt][1] = *(const uint32_t*)(Al + off + 8*BG_ROWB);
                alo[mt][2] = *(const uint32_t*)(Al + off + 16);
                alo[mt][3] = *(const uint32_t*)(Al + off + 8*BG_ROWB + 16);
            }
#pragma unroll
            for (int nt = 0; nt < 4; ++nt) {
                const uint32_t off = (uint32_t)(n0 + nt*8 + qrow) * BG_ROWB + kb + qk4;
                bhi[nt][0] = *(const uint32_t*)(Bh + off);
                bhi[nt][1] = *(const uint32_t*)(Bh + off + 16);
                blo[nt][0] = *(const uint32_t*)(Bl + off);
                blo[nt][1] = *(const uint32_t*)(Bl + off + 16);
            }
#pragma unroll
            for (int mt = 0; mt < 4; ++mt)
#pragma unroll
                for (int nt = 0; nt < 4; ++nt) {
                    mma16816(acc[mt][nt], ahi[mt], bhi[nt]);
                    mma16816(acc[mt][nt], ahi[mt], blo[nt]);
                    mma16816(acc[mt][nt], alo[mt], bhi[nt]);
                }
        }
        __syncthreads();
        if (t + 3 < nch) issue_stage(t + 3);
        else cp_commit();
    }

#pragma unroll
    for (int mt = 0; mt < 4; ++mt) {
        const int r0 = bm + m0 + mt*16 + qrow;
#pragma unroll
        for (int nt = 0; nt < 4; ++nt) {
            const int c = bn + n0 + nt*8 + (lane & 3) * 2;
            float2 v0 = make_float2(acc[mt][nt][0], acc[mt][nt][1]);
            float2 v1 = make_float2(acc[mt][nt][2], acc[mt][nt][3]);
            if (mode == 1) {
                const float* q0 = R + (size_t)r0 * N + c;
                const float* q1 = R + (size_t)(r0 + 8) * N + c;
                v0.x += q0[0]; v0.y += q0[1];
                v1.x += q1[0]; v1.y += q1[1];
            } else if (mode == 2) {
                v0.x *= 2.f; v0.y *= 2.f; v1.x *= 2.f; v1.y *= 2.f;
            }
            if (Cf) {
                *(float2*)(Cf + (size_t)r0 * N + c) = v0;
                *(float2*)(Cf + (size_t)(r0 + 8) * N + c) = v1;
            }
            if (Chi) {
                __nv_bfloat162 h0 = __floats2bfloat162_rn(v0.x, v0.y);
                __nv_bfloat162 h1 = __floats2bfloat162_rn(v1.x, v1.y);
                float2 f0 = __bfloat1622float2(h0);
                float2 f1 = __bfloat1622float2(h1);
                __nv_bfloat162 l0 = __floats2bfloat162_rn(v0.x - f0.x, v0.y - f0.y);
                __nv_bfloat162 l1 = __floats2bfloat162_rn(v1.x - f1.x, v1.y - f1.y);
                *(__nv_bfloat162*)(Chi + (size_t)r0 * N + c) = h0;
                *(__nv_bfloat162*)(Chi + (size_t)(r0 + 8) * N + c) = h1;
                *(__nv_bfloat162*)(Clo + (size_t)r0 * N + c) = l0;
                *(__nv_bfloat162*)(Clo + (size_t)(r0 + 8) * N + c) = l1;
            }
        }
    }
}

// ============ fp16x2 GEMM (MLP path): A split hi/lo, W single fp16 ============
// mode 0: store fp32; mode 1: +R -> fp32; mode 5: silu(R)*acc -> fp16 split
#define HG_STAGE  (3*BG_BUF)
#define HG_SMEM   (3*HG_STAGE)

__global__ __launch_bounds__(256) void hgemm_kernel(
    const __half* __restrict__ Ahi, const __half* __restrict__ Alo,
    const __half* __restrict__ W,
    const float* __restrict__ R, float* __restrict__ Cf,
    __half* __restrict__ Chi, __half* __restrict__ Clo,
    int M, int N, int K, int mode)
{
    extern __shared__ char sm_c[];
    const uint32_t smb = smem_u32(sm_c);

    const int tid = threadIdx.x;
    const int wid = tid >> 5;
    const int lane = tid & 31;
    const int bm = blockIdx.y * 128, bn = blockIdx.x * 128;
    const int m0 = (wid >> 2) * 64;
    const int n0 = (wid & 3) * 32;
    const int qrow = lane >> 2;
    const int qk4 = (lane & 3) * 4;

    const int nch = K >> 5;

    auto issue_stage = [&](int t) {
        const int k0 = t * 32;
        const uint32_t sb = smb + (uint32_t)(t % 3) * HG_STAGE;
#pragma unroll
        for (int c = 0; c < 2; ++c) {
            const int idx = tid + c * 256;
            const int row = idx >> 2, q = idx & 3;
            const uint32_t so = (uint32_t)row * BG_ROWB + q * 16;
            const size_t goA = (size_t)(bm + row) * K + k0 + q * 8;
            const size_t goB = (size_t)(bn + row) * K + k0 + q * 8;
            cp16(sb + so,            Ahi + goA);
            cp16(sb + BG_BUF + so,   Alo + goA);
            cp16(sb + 2*BG_BUF + so, W + goB);
        }
        cp_commit();
    };

    issue_stage(0); issue_stage(1); issue_stage(2);

    float acc[4][4][4];
#pragma unroll
    for (int a = 0; a < 4; ++a)
#pragma unroll
        for (int b = 0; b < 4; ++b)
#pragma unroll
            for (int c = 0; c < 4; ++c) acc[a][b][c] = 0.f;

    for (int t = 0; t < nch; ++t) {
        cp_wait2();
        __syncthreads();
        const char* Ah = sm_c + (t % 3) * HG_STAGE;
        const char* Al = Ah + BG_BUF;
        const char* Bh = Ah + 2*BG_BUF;
#pragma unroll
        for (int kb = 0; kb <= 32; kb += 32) {
            uint32_t ahi[4][4], alo[4][4], bh[4][2];
#pragma unroll
            for (int mt = 0; mt < 4; ++mt) {
                const uint32_t off = (uint32_t)(m0 + mt*16 + qrow) * BG_ROWB + kb + qk4;
                ahi[mt][0] = *(const uint32_t*)(Ah + off);
                ahi[mt][1] = *(const uint32_t*)(Ah + off + 8*BG_ROWB);
                ahi[mt][2] = *(const uint32_t*)(Ah + off + 16);
                ahi[mt][3] = *(const uint32_t*)(Ah + off + 8*BG_ROWB + 16);
                alo[mt][0] = *(const uint32_t*)(Al + off);
                alo[mt][1] = *(const uint32_t*)(Al + off + 8*BG_ROWB);
                alo[mt][2] = *(const uint32_t*)(Al + off + 16);
                alo[mt][3] = *(const uint32_t*)(Al + off + 8*BG_ROWB + 16);
            }
#pragma unroll
            for (int nt = 0; nt < 4; ++nt) {
                const uint32_t off = (uint32_t)(n0 + nt*8 + qrow) * BG_ROWB + kb + qk4;
                bh[nt][0] = *(const uint32_t*)(Bh + off);
                bh[nt][1] = *(const uint32_t*)(Bh + off + 16);
            }
#pragma unroll
            for (int mt = 0; mt < 4; ++mt)
#pragma unroll
                for (int nt = 0; nt < 4; ++nt) {
                    mma16816h(acc[mt][nt], ahi[mt], bh[nt]);
                    mma16816h(acc[mt][nt], alo[mt], bh[nt]);
                }
        }
        __syncthreads();
        if (t + 3 < nch) issue_stage(t + 3);
        else cp_commit();
    }

#pragma unroll
    for (int mt = 0; mt < 4; ++mt) {
        const int r0 = bm + m0 + mt*16 + qrow;
#pragma unroll
        for (int nt = 0; nt < 4; ++nt) {
            const int c = bn + n0 + nt*8 + (lane & 3) * 2;
            float2 v0 = make_float2(acc[mt][nt][0], acc[mt][nt][1]);
            float2 v1 = make_float2(acc[mt][nt][2], acc[mt][nt][3]);
            if (mode == 1) {
                const float* q0 = R + (size_t)r0 * N + c;
                const float* q1 = R + (size_t)(r0 + 8) * N + c;
                v0.x += q0[0]; v0.y += q0[1];
                v1.x += q1[0]; v1.y += q1[1];
            } else if (mode == 5) {
                const float* q0 = R + (size_t)r0 * N + c;
                const float* q1 = R + (size_t)(r0 + 8) * N + c;
                const float s0 = q0[0], s1 = q0[1], s2 = q1[0], s3 = q1[1];
                v0.x *= s0 / (1.f + __expf(-s0));
                v0.y *= s1 / (1.f + __expf(-s1));
                v1.x *= s2 / (1.f + __expf(-s2));
                v1.y *= s3 / (1.f + __expf(-s3));
            }
            if (Cf) {
                *(float2*)(Cf + (size_t)r0 * N + c) = v0;
                *(float2*)(Cf + (size_t)(r0 + 8) * N + c) = v1;
            }
            if (Chi) {
                __half2 h0 = __floats2half2_rn(v0.x, v0.y);
                __half2 h1 = __floats2half2_rn(v1.x, v1.y);
                float2 f0 = __half22float2(h0);
                float2 f1 = __half22float2(h1);
                __half2 l0 = __floats2half2_rn(v0.x - f0.x, v0.y - f0.y);
                __half2 l1 = __floats2half2_rn(v1.x - f1.x, v1.y - f1.y);
                *(__half2*)(Chi + (size_t)r0 * N + c) = h0;
                *(__half2*)(Chi + (size_t)(r0 + 8) * N + c) = h1;
                *(__half2*)(Clo + (size_t)r0 * N + c) = l0;
                *(__half2*)(Clo + (size_t)(r0 + 8) * N + c) = l1;
            }
        }
    }
}

// ---------------- rmsnorm: fp32 out (optional) + fused bf16 hi/lo split ----------------
__global__ __launch_bounds__(256) void rmsnorm_kernel(
    const float* __restrict__ x, const float* __restrict__ g,
    float* __restrict__ outf, __nv_bfloat162* __restrict__ hi,
    __nv_bfloat162* __restrict__ lo)
{
    __shared__ float red[8];
    __shared__ float sscale;
    const int row = blockIdx.x;
    const int t = threadIdx.x;
    const float4* xr = (const float4*)(x + (size_t)row * 1024);
    float4 v = xr[t];
    float ss = v.x*v.x + v.y*v.y + v.z*v.z + v.w*v.w;
#pragma unroll
    for (int o = 16; o; o >>= 1) ss += __shfl_xor_sync(0xffffffffu, ss, o);
    if ((t & 31) == 0) red[t >> 5] = ss;
    __syncthreads();
    if (t == 0) {
        float s = 0.f;
#pragma unroll
        for (int i = 0; i < 8; ++i) s += red[i];
        sscale = rsqrtf(s * (1.0f/1024.0f) + 1e-6f);
    }
    __syncthreads();
    const float sc = sscale;
    float4 gv = ((const float4*)g)[t];
    float4 o;
    o.x = v.x*sc*gv.x; o.y = v.y*sc*gv.y; o.z = v.z*sc*gv.z; o.w = v.w*sc*gv.w;
    if (outf) ((float4*)(outf + (size_t)row * 1024))[t] = o;
    __nv_bfloat162 h01 = __floats2bfloat162_rn(o.x, o.y);
    __nv_bfloat162 h23 = __floats2bfloat162_rn(o.z, o.w);
    float2 f01 = __bfloat1622float2(h01);
    float2 f23 = __bfloat1622float2(h23);
    __nv_bfloat162 l01 = __floats2bfloat162_rn(o.x - f01.x, o.y - f01.y);
    __nv_bfloat162 l23 = __floats2bfloat162_rn(o.z - f23.x, o.w - f23.y);
    const size_t p = (size_t)row * 512 + t * 2;
    hi[p] = h01; hi[p+1] = h23;
    lo[p] = l01; lo[p+1] = l23;
}

// ---------------- rmsnorm -> fp16 hi/lo split (MLP path) ----------------
__global__ __launch_bounds__(256) void rmsnorm_h_kernel(
    const float* __restrict__ x, const float* __restrict__ g,
    __half2* __restrict__ hi, __half2* __restrict__ lo)
{
    __shared__ float red[8];
    __shared__ float sscale;
    const int row = blockIdx.x;
    const int t = threadIdx.x;
    const float4* xr = (const float4*)(x + (size_t)row * 1024);
    float4 v = xr[t];
    float ss = v.x*v.x + v.y*v.y + v.z*v.z + v.w*v.w;
#pragma unroll
    for (int o = 16; o; o >>= 1) ss += __shfl_xor_sync(0xffffffffu, ss, o);
    if ((t & 31) == 0) red[t >> 5] = ss;
    __syncthreads();
    if (t == 0) {
        float s = 0.f;
#pragma unroll
        for (int i = 0; i < 8; ++i) s += red[i];
        sscale = rsqrtf(s * (1.0f/1024.0f) + 1e-6f);
    }
    __syncthreads();
    const float sc = sscale;
    float4 gv = ((const float4*)g)[t];
    float4 o;
    o.x = v.x*sc*gv.x; o.y = v.y*sc*gv.y; o.z = v.z*sc*gv.z; o.w = v.w*sc*gv.w;
    __half2 h01 = __floats2half2_rn(o.x, o.y);
    __half2 h23 = __floats2half2_rn(o.z, o.w);
    float2 f01 = __half22float2(h01);
    float2 f23 = __half22float2(h23);
    __half2 l01 = __floats2half2_rn(o.x - f01.x, o.y - f01.y);
    __half2 l23 = __floats2half2_rn(o.z - f23.x, o.w - f23.y);
    const size_t p = (size_t)row * 512 + t * 2;
    hi[p] = h01; hi[p+1] = h23;
    lo[p] = l01; lo[p+1] = l23;
}

// ---------------- lambda ----------------
__global__ void lambda_kernel(const float* __restrict__ lq1, const float* __restrict__ lk1,
                              const float* __restrict__ lq2, const float* __restrict__ lk2,
                              float* __restrict__ lam)
{
    const int h = blockIdx.x;
    const int lane = threadIdx.x;
    float s1 = 0.f, s2 = 0.f;
    for (int d = lane; d < 64; d += 32) {
        s1 += lq1[h*64 + d] * lk1[h*64 + d];
        s2 += lq2[h*64 + d] * lk2[h*64 + d];
    }
#pragma unroll
    for (int o = 16; o; o >>= 1) {
        s1 += __shfl_xor_sync(0xffffffffu, s1, o);
        s2 += __shfl_xor_sync(0xffffffffu, s2, o);
    }
    if (lane == 0) lam[h] = expf(s1) - expf(s2) + 0.8f;
}

// ================ tensor-core flash diff-attention (bf16x3) ================
#define FLM_ROWB 144u
#define SQ1H 0u
#define SQ2H 18432u
#define SK1H 36864u
#define SK2H 55296u
#define SVH  73728u
#define FLM_SMEM 92160
#define SOEX 36864u

__global__ __launch_bounds__(256, 2) void flash_mma_kernel(
    const float* __restrict__ Q, const float* __restrict__ Kg,
    const float* __restrict__ Vg, const float* __restrict__ lamp,
    __nv_bfloat16* __restrict__ Ohi, __nv_bfloat16* __restrict__ Olo,
    int Sq, int Sk, int causal)
{
    extern __shared__ char smf[];
    const uint32_t smb = smem_u32(smf);
    const int tid = threadIdx.x, wid = tid >> 5, lane = tid & 31;
    const int g = lane >> 2, qq = lane & 3;
    const int qt = blockIdx.x, h = blockIdx.y, b = blockIdx.z;
    const int mat = wid >> 2;
    const int slab = (wid & 3) * 16;

#pragma unroll
    for (int u = 0; u < 8; ++u) {
        const int idx = tid + u * 256;
        const int r = idx >> 5, d0 = (idx & 31) * 4;
        const float4 v = *(const float4*)(Q + ((size_t)(b*Sq + qt*64 + r) * Hh + h) * 128 + d0);
        const uint32_t off = ((d0 < 64) ? SQ1H : SQ2H) + (uint32_t)r * FLM_ROWB + (uint32_t)(d0 & 63) * 2;
        __nv_bfloat162 h01 = __floats2bfloat162_rn(v.x, v.y);
        __nv_bfloat162 h23 = __floats2bfloat162_rn(v.z, v.w);
        float2 f01 = __bfloat1622float2(h01), f23 = __bfloat1622float2(h23);
        __nv_bfloat162 l01 = __floats2bfloat162_rn(v.x - f01.x, v.y - f01.y);
        __nv_bfloat162 l23 = __floats2bfloat162_rn(v.z - f23.x, v.w - f23.y);
        *(__nv_bfloat162*)(smf + off)        = h01;
        *(__nv_bfloat162*)(smf + off + 4)    = h23;
        *(__nv_bfloat162*)(smf + off + 9216) = l01;
        *(__nv_bfloat162*)(smf + off + 9220) = l23;
    }

    float O[8][4];
#pragma unroll
    for (int t = 0; t < 8; ++t)
#pragma unroll
        for (int c = 0; c < 4; ++c) O[t][c] = 0.f;
    float rm[2] = { -1e30f, -1e30f }, rl[2] = { 0.f, 0.f };

    const int nkt = causal ? (qt + 1) : (Sk >> 6);

    for (int kt = 0; kt < nkt; ++kt) {
        __syncthreads();
#pragma unroll
        for (int u = 0; u < 8; ++u) {
            const int idx = tid + u * 256;
            const int r = idx >> 5, d0 = (idx & 31) * 4;
            const float4 v = *(const float4*)(Kg + ((size_t)(b*Sk + kt*64 + r) * Hh + h) * 128 + d0);
            const uint32_t off = ((d0 < 64) ? SK1H : SK2H) + (uint32_t)r * FLM_ROWB + (uint32_t)(d0 & 63) * 2;
            __nv_bfloat162 h01 = __floats2bfloat162_rn(v.x, v.y);
            __nv_bfloat162 h23 = __floats2bfloat162_rn(v.z, v.w);
            float2 f01 = __bfloat1622float2(h01), f23 = __bfloat1622float2(h23);
            __nv_bfloat162 l01 = __floats2bfloat162_rn(v.x - f01.x, v.y - f01.y);
            __nv_bfloat162 l23 = __floats2bfloat162_rn(v.z - f23.x, v.w - f23.y);
            *(__nv_bfloat162*)(smf + off)        = h01;
            *(__nv_bfloat162*)(smf + off + 4)    = h23;
            *(__nv_bfloat162*)(smf + off + 9216) = l01;
            *(__nv_bfloat162*)(smf + off + 9220) = l23;
        }
#pragma unroll
        for (int u = 0; u < 4; ++u) {
            const int idx = tid + u * 256;
            const int key = idx >> 4, d0 = (idx & 15) * 4;
            const float4 v = *(const float4*)(Vg + ((size_t)(b*Sk + kt*64 + key) * Hh + h) * 64 + d0);
            const float vv[4] = { v.x, v.y, v.z, v.w };
#pragma unroll
            for (int j = 0; j < 4; ++j) {
                const float f = vv[j];
                __nv_bfloat16 hb = __float2bfloat16(f);
                __nv_bfloat16 lb = __float2bfloat16(f - __bfloat162float(hb));
                const uint32_t o2 = (uint32_t)(d0 + j) * FLM_ROWB + (uint32_t)key * 2;
                *(__nv_bfloat16*)(smf + SVH + o2) = hb;
                *(__nv_bfloat16*)(smf + SVH + 9216 + o2) = lb;
            }
        }
        __syncthreads();

        float S[8][4];
#pragma unroll
        for (int t = 0; t < 8; ++t)
#pragma unroll
            for (int c = 0; c < 4; ++c) S[t][c] = 0.f;

        const uint32_t qB = smb + (mat ? SQ2H : SQ1H);
        const uint32_t kB = smb + (mat ? SK2H : SK1H);
#pragma unroll
        for (int s = 0; s < 4; ++s) {
            uint32_t ah[4], al[4];
            const uint32_t ao = qB + (uint32_t)(slab + g) * FLM_ROWB + s * 32 + qq * 4;
            ah[0] = lds32(ao);              ah[1] = lds32(ao + 8*FLM_ROWB);
            ah[2] = lds32(ao + 16);         ah[3] = lds32(ao + 8*FLM_ROWB + 16);
            al[0] = lds32(ao + 9216);       al[1] = lds32(ao + 9216 + 8*FLM_ROWB);
            al[2] = lds32(ao + 9216 + 16);  al[3] = lds32(ao + 9216 + 8*FLM_ROWB + 16);
#pragma unroll
            for (int nt = 0; nt < 8; ++nt) {
                const uint32_t bo = kB + (uint32_t)(nt*8 + g) * FLM_ROWB + s * 32 + qq * 4;
                uint32_t bh[2], bl[2];
                bh[0] = lds32(bo);        bh[1] = lds32(bo + 16);
                bl[0] = lds32(bo + 9216); bl[1] = lds32(bo + 9216 + 16);
                mma16816(S[nt], ah, bh);
                mma16816(S[nt], ah, bl);
                mma16816(S[nt], al, bh);
            }
        }

        const bool dg = (causal != 0) && (kt == qt);
        uint32_t pH[8][2], pL[8][2];
#pragma unroll
        for (int j = 0; j < 2; ++j) {
            const int rloc = slab + g + j*8;
            float mx = -1e30f;
#pragma unroll
            for (int t = 0; t < 8; ++t) {
                float* sp = &S[t][j*2];
                sp[0] *= 0.125f; sp[1] *= 0.125f;
                if (dg) {
                    const int c = t*8 + qq*2;
                    if (c > rloc)     sp[0] = -1e9f;
                    if (c + 1 > rloc) sp[1] = -1e9f;
                }
                mx = fmaxf(mx, fmaxf(sp[0], sp[1]));
            }
            mx = fmaxf(mx, __shfl_xor_sync(0xffffffffu, mx, 1));
            mx = fmaxf(mx, __shfl_xor_sync(0xffffffffu, mx, 2));
            const float mn = fmaxf(rm[j], mx);
            const float alw = __expf(rm[j] - mn);
            rm[j] = mn;
            float rs = 0.f;
#pragma unroll
            for (int t = 0; t < 8; ++t) {
                const float p0 = __expf(S[t][j*2]   - mn);
                const float p1 = __expf(S[t][j*2+1] - mn);
                rs += p0 + p1;
                __nv_bfloat162 hp = __floats2bfloat162_rn(p0, p1);
                float2 fp = __bfloat1622float2(hp);
                __nv_bfloat162 lp = __floats2bfloat162_rn(p0 - fp.x, p1 - fp.y);
                pH[t][j] = *(uint32_t*)&hp;
                pL[t][j] = *(uint32_t*)&lp;
            }
            rs += __shfl_xor_sync(0xffffffffu, rs, 1);
            rs += __shfl_xor_sync(0xffffffffu, rs, 2);
            rl[j] = rl[j] * alw + rs;
#pragma unroll
            for (int t = 0; t < 8; ++t) { O[t][j*2] *= alw; O[t][j*2+1] *= alw; }
        }

#pragma unroll
        for (int s = 0; s < 4; ++s) {
            const uint32_t aP[4]  = { pH[2*s][0], pH[2*s][1], pH[2*s+1][0], pH[2*s+1][1] };
            const uint32_t aPl[4] = { pL[2*s][0], pL[2*s][1], pL[2*s+1][0], pL[2*s+1][1] };
#pragma unroll
            for (int nt = 0; nt < 8; ++nt) {
                const uint32_t bo = smb + SVH + (uint32_t)(nt*8 + g) * FLM_ROWB + s * 32 + qq * 4;
                uint32_t bh[2], bl[2];
                bh[0] = lds32(bo);        bh[1] = lds32(bo + 16);
                bl[0] = lds32(bo + 9216); bl[1] = lds32(bo + 9216 + 16);
                mma16816(O[nt], aP,  bh);
                mma16816(O[nt], aP,  bl);
                mma16816(O[nt], aPl, bh);
            }
        }
    }

    __syncthreads();
    if (mat == 1) {
#pragma unroll
        for (int j = 0; j < 2; ++j) {
            const float inv = 1.f / rl[j];
            const int row = slab + g + j*8;
#pragma unroll
            for (int t = 0; t < 8; ++t) {
                const int col = t*8 + qq*2;
                float2 w = make_float2(O[t][j*2] * inv, O[t][j*2+1] * inv);
                *(float2*)(smf + SOEX + ((uint32_t)row * 68 + col) * 4) = w;
            }
        }
    }
    __syncthreads();
    if (mat == 0) {
        const float lam = lamp[h];
#pragma unroll
        for (int j = 0; j < 2; ++j) {
            const float inv = 1.f / rl[j];
            const int row = slab + g + j*8;
            float vbuf[16];
            float ss = 0.f;
#pragma unroll
            for (int t = 0; t < 8; ++t) {
                const int col = t*8 + qq*2;
                const float2 w = *(const float2*)(smf + SOEX + ((uint32_t)row * 68 + col) * 4);
                const float v0 = O[t][j*2]   * inv - lam * w.x;
                const float v1 = O[t][j*2+1] * inv - lam * w.y;
                vbuf[2*t] = v0; vbuf[2*t+1] = v1;
                ss += v0*v0 + v1*v1;
            }
            ss += __shfl_xor_sync(0xffffffffu, ss, 1);
            ss += __shfl_xor_sync(0xffffffffu, ss, 2);
            const float scl = rsqrtf(ss * (1.0f/64.0f) + 1e-6f) * 0.2f;
            const size_t ob = ((size_t)(b*Sq + qt*64 + row) * Hh + h) * 64;
#pragma unroll
            for (int t = 0; t < 8; ++t) {
                const int col = t*8 + qq*2;
                const float v0 = vbuf[2*t] * scl, v1 = vbuf[2*t+1] * scl;
                __nv_bfloat162 hh = __floats2bfloat162_rn(v0, v1);
                float2 fh = __bfloat1622float2(hh);
                __nv_bfloat162 ll = __floats2bfloat162_rn(v0 - fh.x, v1 - fh.y);
                *(__nv_bfloat162*)(Ohi + ob + col) = hh;
                *(__nv_bfloat162*)(Olo + ob + col) = ll;
            }
        }
    }
}

// ---------------- host-side launch helpers ----------------
static __nv_bfloat16 *s_whi, *s_wlo, *s_ahi, *s_alo, *s_bhi, *s_blo;
static __half *s_wh;

static void splitW(const float* W, uint32_t off, int K, int N) {
    split_t_kernel<<<dim3(N/32, K/32), dim3(32, 8)>>>(W, s_whi + off, s_wlo + off, K, N);
}
static void splitWh(const float* W, uint32_t off, int K, int N) {
    split_t_h_kernel<<<dim3(N/32, K/32), dim3(32, 8)>>>(W, s_wh + off, K, N);
}
static void gemm(const __nv_bfloat16* ahi, const __nv_bfloat16* alo, uint32_t woff,
                 const float* R, float* Cf, __nv_bfloat16* chi, __nv_bfloat16* clo,
                 int M, int N, int K, int mode)
{
    dim3 grid(N / 128, M / 128);
    bgemm_kernel<<<grid, 256, BG_SMEM>>>(ahi, alo, s_whi + woff, s_wlo + woff,
                                         R, Cf, chi, clo, M, N, K, mode);
}
static void hgemm(const __half* ahi, const __half* alo, uint32_t woff,
                  const float* R, float* Cf, __half* chi, __half* clo,
                  int M, int N, int K, int mode)
{
    dim3 grid(N / 128, M / 128);
    hgemm_kernel<<<grid, 256, HG_SMEM>>>(ahi, alo, s_wh + woff,
                                         R, Cf, chi, clo, M, N, K, mode);
}

extern "C" void kernel_launch(void* const* d_in, const int* in_sizes, int n_in,
                              void* d_out, int out_size)
{
    const float* x    = (const float*)d_in[0];
    const float* enc  = (const float*)d_in[1];
    const float* Wq_s = (const float*)d_in[2];
    const float* Wk_s = (const float*)d_in[3];
    const float* Wv_s = (const float*)d_in[4];
    const float* Wo_s = (const float*)d_in[5];
    const float* lq1s = (const float*)d_in[6];
    const float* lk1s = (const float*)d_in[7];
    const float* lq2s = (const float*)d_in[8];
    const float* lk2s = (const float*)d_in[9];
    const float* Wq_c = (const float*)d_in[10];
    const float* Wk_c = (const float*)d_in[11];
    const float* Wv_c = (const float*)d_in[12];
    const float* Wo_c = (const float*)d_in[13];
    const float* lq1c = (const float*)d_in[14];
    const float* lk1c = (const float*)d_in[15];
    const float* lq2c = (const float*)d_in[16];
    const float* lk2c = (const float*)d_in[17];
    const float* grms = (const float*)d_in[18];
    const float* W1   = (const float*)d_in[19];
    const float* W2   = (const float*)d_in[20];
    const float* W3   = (const float*)d_in[21];
    float* out = (float*)d_out;

    float *hn, *q, *k, *v, *h2, *m1, *lam;
    cudaGetSymbolAddress((void**)&hn,  g_hn);
    cudaGetSymbolAddress((void**)&q,   g_q);
    cudaGetSymbolAddress((void**)&k,   g_k);
    cudaGetSymbolAddress((void**)&v,   g_v);
    cudaGetSymbolAddress((void**)&h2,  g_h2);
    cudaGetSymbolAddress((void**)&m1,  g_m1);
    cudaGetSymbolAddress((void**)&lam, g_lam);
    cudaGetSymbolAddress((void**)&s_whi, g_whi);
    cudaGetSymbolAddress((void**)&s_wlo, g_wlo);
    cudaGetSymbolAddress((void**)&s_ahi, g_ahi);
    cudaGetSymbolAddress((void**)&s_alo, g_alo);
    cudaGetSymbolAddress((void**)&s_bhi, g_bhi);
    cudaGetSymbolAddress((void**)&s_blo, g_blo);
    cudaGetSymbolAddress((void**)&s_wh,  g_wh);

    cudaFuncSetAttribute(flash_mma_kernel,
                         cudaFuncAttributeMaxDynamicSharedMemorySize, FLM_SMEM);
    cudaFuncSetAttribute(bgemm_kernel,
                         cudaFuncAttributeMaxDynamicSharedMemorySize, BG_SMEM);
    cudaFuncSetAttribute(hgemm_kernel,
                         cudaFuncAttributeMaxDynamicSharedMemorySize, HG_SMEM);

    // ---- weight prep: bf16 hi/lo (attention path), fp16 single (MLP) ----
    splitW(Wq_s, OW_QS, 1024, 2048);
    splitW(Wk_s, OW_KS, 1024, 2048);
    splitW(Wv_s, OW_VS, 1024, 1024);
    splitW(Wo_s, OW_OS, 1024, 1024);
    splitW(Wq_c, OW_QC, 1024, 2048);
    splitW(Wk_c, OW_KC, 1024, 2048);
    splitW(Wv_c, OW_VC, 1024, 1024);
    splitW(Wo_c, OW_OC, 1024, 1024);
    splitWh(W1, OHW1, 1024, 4096);
    splitWh(W2, OHW2, 1024, 4096);
    splitWh(W3, OHW3, 4096, 1024);

    // h = rmsnorm(x, g) -> fp32 hn (residual) + bf16 split in A
    rmsnorm_kernel<<<ROWS, 256>>>(x, grms, hn,
        (__nv_bfloat162*)s_ahi, (__nv_bfloat162*)s_alo);

    // ---- self diff-attention (causal) ----
    gemm(s_ahi, s_alo, OW_QS, nullptr, q, nullptr, nullptr, ROWS, 2048, 1024, 0);
    gemm(s_ahi, s_alo, OW_KS, nullptr, k, nullptr, nullptr, ROWS, 2048, 1024, 0);
    gemm(s_ahi, s_alo, OW_VS, nullptr, v, nullptr, nullptr, ROWS, 1024, 1024, 0);
    lambda_kernel<<<Hh, 32>>>(lq1s, lk1s, lq2s, lk2s, lam);
    flash_mma_kernel<<<dim3(Tt/64, Hh, Bb), 256, FLM_SMEM>>>(q, k, v, lam,
        s_bhi, s_blo, Tt, Tt, 1);
    // h1 = ao @ Wo_s + hn  -> bf16 split into A
    gemm(s_bhi, s_blo, OW_OS, hn, nullptr, s_ahi, s_alo, ROWS, 1024, 1024, 1);

    // ---- cross diff-attention (not causal) ----
    gemm(s_ahi, s_alo, OW_QC, nullptr, q, nullptr, nullptr, ROWS, 2048, 1024, 0);
    split_kernel<<<(ROWS*1024/4)/256, 256>>>((const float4*)enc,
        (__nv_bfloat162*)s_bhi, (__nv_bfloat162*)s_blo, ROWS*1024/4);
    gemm(s_bhi, s_blo, OW_KC, nullptr, k, nullptr, nullptr, ROWS, 2048, 1024, 0);
    gemm(s_bhi, s_blo, OW_VC, nullptr, v, nullptr, nullptr, ROWS, 1024, 1024, 0);
    lambda_kernel<<<Hh, 32>>>(lq1c, lk1c, lq2c, lk2c, lam + 16);
    flash_mma_kernel<<<dim3(Tt/64, Hh, Bb), 256, FLM_SMEM>>>(q, k, v, lam + 16,
        s_ahi, s_alo, Tt, Tt, 0);
    // h2 = 2 * (ao @ Wo_c) -> fp32 (residual + rmsnorm input)
    gemm(s_ahi, s_alo, OW_OC, nullptr, h2, nullptr, nullptr, ROWS, 1024, 1024, 2);

    // ---- MLP (fp16 2-term path) ----
    // rmsnorm(h2) -> fp16 split into B buffers (reinterpreted)
    rmsnorm_h_kernel<<<ROWS, 256>>>(h2, grms,
        (__half2*)s_bhi, (__half2*)s_blo);
    // m1 = hn2 @ W1 (fp32, silu input)
    hgemm((const __half*)s_bhi, (const __half*)s_blo, OHW1,
          nullptr, m1, nullptr, nullptr, ROWS, DFF, 1024, 0);
    // silu(m1) * (hn2 @ W2) -> fp16 split into A buffers
    hgemm((const __half*)s_bhi, (const __half*)s_blo, OHW2,
          m1, nullptr, (__half*)s_ahi, (__half*)s_alo, ROWS, DFF, 1024, 5);
    // out = (silu·) @ W3 + h2
    hgemm((const __half*)s_ahi, (const __half*)s_alo, OHW3,
          h2, out, nullptr, nullptr, ROWS, 1024, DFF, 1);
}

// round 11
// speedup vs baseline: 1.7312x; 1.1621x over previous
#include <cuda_runtime.h>
#include <cuda_bf16.h>
#include <cuda_fp16.h>
#include <math.h>
#include <stdint.h>

// ---------------- problem dims (fixed) ----------------
#define Bb   4
#define Tt   1024
#define Dd   1024
#define Hh   16
#define HSs  64
#define DFF  4096
#define ROWS (Bb*Tt)      // 4096

// ---------------- scratch (device globals; no allocs allowed) ----------------
__device__ float g_hn [ROWS*Dd];
__device__ float g_q  [ROWS*2048];
__device__ float g_k  [ROWS*2048];
__device__ float g_v  [ROWS*1024];
__device__ float g_h2 [ROWS*Dd];
__device__ float g_m1 [ROWS*DFF];
__device__ float g_lam[32];

// fp16 activation split buffers
#define NA_TOT (ROWS*DFF)
__device__ __half g_ahi[NA_TOT];
__device__ __half g_alo[NA_TOT];
__device__ __half g_bhi[NA_TOT];
__device__ __half g_blo[NA_TOT];

// fp16 weights (single term), transposed [N][K]
#define NHW_TOT (24u*1024u*1024u)
__device__ __half g_wh[NHW_TOT];
#define OW_QS (0u)
#define OW_KS (2u*1024u*1024u)
#define OW_VS (4u*1024u*1024u)
#define OW_OS (5u*1024u*1024u)
#define OW_QC (6u*1024u*1024u)
#define OW_KC (8u*1024u*1024u)
#define OW_VC (10u*1024u*1024u)
#define OW_OC (11u*1024u*1024u)
#define OW_W1 (12u*1024u*1024u)
#define OW_W2 (16u*1024u*1024u)
#define OW_W3 (20u*1024u*1024u)

// ================= small helpers =================
__device__ __forceinline__ uint32_t smem_u32(const void* p) {
    uint32_t a;
    asm("{ .reg .u64 t; cvta.to.shared.u64 t, %1; cvt.u32.u64 %0, t; }" : "=r"(a) : "l"(p));
    return a;
}
__device__ __forceinline__ void cp16(uint32_t dst, const void* src) {
    asm volatile("cp.async.cg.shared.global [%0], [%1], 16;" :: "r"(dst), "l"(src) : "memory");
}
__device__ __forceinline__ void cp_commit() {
    asm volatile("cp.async.commit_group;" ::: "memory");
}
__device__ __forceinline__ void cp_wait2() {
    asm volatile("cp.async.wait_group 2;" ::: "memory");
}
__device__ __forceinline__ void mma16816(float* d, const uint32_t* a, const uint32_t* b) {
    asm volatile(
        "mma.sync.aligned.m16n8k16.row.col.f32.bf16.bf16.f32 "
        "{%0,%1,%2,%3}, {%4,%5,%6,%7}, {%8,%9}, {%0,%1,%2,%3};"
        : "+f"(d[0]), "+f"(d[1]), "+f"(d[2]), "+f"(d[3])
        : "r"(a[0]), "r"(a[1]), "r"(a[2]), "r"(a[3]), "r"(b[0]), "r"(b[1]));
}
__device__ __forceinline__ void mma16816h(float* d, const uint32_t* a, const uint32_t* b) {
    asm volatile(
        "mma.sync.aligned.m16n8k16.row.col.f32.f16.f16.f32 "
        "{%0,%1,%2,%3}, {%4,%5,%6,%7}, {%8,%9}, {%0,%1,%2,%3};"
        : "+f"(d[0]), "+f"(d[1]), "+f"(d[2]), "+f"(d[3])
        : "r"(a[0]), "r"(a[1]), "r"(a[2]), "r"(a[3]), "r"(b[0]), "r"(b[1]));
}
__device__ __forceinline__ uint32_t lds32(uint32_t addr) {
    uint32_t v;
    asm volatile("ld.shared.b32 %0, [%1];" : "=r"(v) : "r"(addr));
    return v;
}

// ============ activation split: fp32 -> fp16 hi + fp16 lo ============
__global__ __launch_bounds__(256) void split_h_kernel(
    const float4* __restrict__ in, __half2* __restrict__ hi,
    __half2* __restrict__ lo, int n4)
{
    const int i = blockIdx.x * blockDim.x + threadIdx.x;
    if (i >= n4) return;
    float4 v = in[i];
    __half2 h01 = __floats2half2_rn(v.x, v.y);
    __half2 h23 = __floats2half2_rn(v.z, v.w);
    float2 f01 = __half22float2(h01);
    float2 f23 = __half22float2(h23);
    __half2 l01 = __floats2half2_rn(v.x - f01.x, v.y - f01.y);
    __half2 l23 = __floats2half2_rn(v.z - f23.x, v.w - f23.y);
    hi[2*i] = h01; hi[2*i+1] = h23;
    lo[2*i] = l01; lo[2*i+1] = l23;
}

// ============ weight transpose: single fp16 ============
__global__ __launch_bounds__(256) void split_t_h_kernel(
    const float* __restrict__ B, __half* __restrict__ th, int K, int N)
{
    __shared__ float tile[32][33];
    const int tx = threadIdx.x, ty = threadIdx.y;
    const int n0 = blockIdx.x * 32, k0 = blockIdx.y * 32;
#pragma unroll
    for (int j = ty; j < 32; j += 8)
        tile[j][tx] = B[(size_t)(k0 + j) * N + n0 + tx];
    __syncthreads();
#pragma unroll
    for (int j = ty; j < 32; j += 8) {
        const size_t o = (size_t)(n0 + j) * K + k0 + tx;
        th[o] = __float2half(tile[tx][j]);
    }
}

// ============ fp16x2 GEMM: A split hi/lo, W single fp16 ============
// mode 0: store fp32; 1: +R; 2: *2; 5: silu(R)*acc
// optional fp16 hi/lo split output (Chi/Clo)
#define BG_ROWB   80
#define BG_BUF    (128*BG_ROWB)
#define HG_STAGE  (3*BG_BUF)
#define HG_SMEM   (3*HG_STAGE)

__global__ __launch_bounds__(256) void hgemm_kernel(
    const __half* __restrict__ Ahi, const __half* __restrict__ Alo,
    const __half* __restrict__ W,
    const float* __restrict__ R, float* __restrict__ Cf,
    __half* __restrict__ Chi, __half* __restrict__ Clo,
    int M, int N, int K, int mode)
{
    extern __shared__ char sm_c[];
    const uint32_t smb = smem_u32(sm_c);

    const int tid = threadIdx.x;
    const int wid = tid >> 5;
    const int lane = tid & 31;
    const int bm = blockIdx.y * 128, bn = blockIdx.x * 128;
    const int m0 = (wid >> 2) * 64;
    const int n0 = (wid & 3) * 32;
    const int qrow = lane >> 2;
    const int qk4 = (lane & 3) * 4;

    const int nch = K >> 5;

    auto issue_stage = [&](int t) {
        const int k0 = t * 32;
        const uint32_t sb = smb + (uint32_t)(t % 3) * HG_STAGE;
#pragma unroll
        for (int c = 0; c < 2; ++c) {
            const int idx = tid + c * 256;
            const int row = idx >> 2, q = idx & 3;
            const uint32_t so = (uint32_t)row * BG_ROWB + q * 16;
            const size_t goA = (size_t)(bm + row) * K + k0 + q * 8;
            const size_t goB = (size_t)(bn + row) * K + k0 + q * 8;
            cp16(sb + so,            Ahi + goA);
            cp16(sb + BG_BUF + so,   Alo + goA);
            cp16(sb + 2*BG_BUF + so, W + goB);
        }
        cp_commit();
    };

    issue_stage(0); issue_stage(1); issue_stage(2);

    float acc[4][4][4];
#pragma unroll
    for (int a = 0; a < 4; ++a)
#pragma unroll
        for (int b = 0; b < 4; ++b)
#pragma unroll
            for (int c = 0; c < 4; ++c) acc[a][b][c] = 0.f;

    for (int t = 0; t < nch; ++t) {
        cp_wait2();
        __syncthreads();
        const char* Ah = sm_c + (t % 3) * HG_STAGE;
        const char* Al = Ah + BG_BUF;
        const char* Bh = Ah + 2*BG_BUF;
#pragma unroll
        for (int kb = 0; kb <= 32; kb += 32) {
            uint32_t ahi[4][4], alo[4][4], bh[4][2];
#pragma unroll
            for (int mt = 0; mt < 4; ++mt) {
                const uint32_t off = (uint32_t)(m0 + mt*16 + qrow) * BG_ROWB + kb + qk4;
                ahi[mt][0] = *(const uint32_t*)(Ah + off);
                ahi[mt][1] = *(const uint32_t*)(Ah + off + 8*BG_ROWB);
                ahi[mt][2] = *(const uint32_t*)(Ah + off + 16);
                ahi[mt][3] = *(const uint32_t*)(Ah + off + 8*BG_ROWB + 16);
                alo[mt][0] = *(const uint32_t*)(Al + off);
                alo[mt][1] = *(const uint32_t*)(Al + off + 8*BG_ROWB);
                alo[mt][2] = *(const uint32_t*)(Al + off + 16);
                alo[mt][3] = *(const uint32_t*)(Al + off + 8*BG_ROWB + 16);
            }
#pragma unroll
            for (int nt = 0; nt < 4; ++nt) {
                const uint32_t off = (uint32_t)(n0 + nt*8 + qrow) * BG_ROWB + kb + qk4;
                bh[nt][0] = *(const uint32_t*)(Bh + off);
                bh[nt][1] = *(const uint32_t*)(Bh + off + 16);
            }
#pragma unroll
            for (int mt = 0; mt < 4; ++mt)
#pragma unroll
                for (int nt = 0; nt < 4; ++nt) {
                    mma16816h(acc[mt][nt], ahi[mt], bh[nt]);
                    mma16816h(acc[mt][nt], alo[mt], bh[nt]);
                }
        }
        __syncthreads();
        if (t + 3 < nch) issue_stage(t + 3);
        else cp_commit();
    }

#pragma unroll
    for (int mt = 0; mt < 4; ++mt) {
        const int r0 = bm + m0 + mt*16 + qrow;
#pragma unroll
        for (int nt = 0; nt < 4; ++nt) {
            const int c = bn + n0 + nt*8 + (lane & 3) * 2;
            float2 v0 = make_float2(acc[mt][nt][0], acc[mt][nt][1]);
            float2 v1 = make_float2(acc[mt][nt][2], acc[mt][nt][3]);
            if (mode == 1) {
                const float* q0 = R + (size_t)r0 * N + c;
                const float* q1 = R + (size_t)(r0 + 8) * N + c;
                v0.x += q0[0]; v0.y += q0[1];
                v1.x += q1[0]; v1.y += q1[1];
            } else if (mode == 2) {
                v0.x *= 2.f; v0.y *= 2.f; v1.x *= 2.f; v1.y *= 2.f;
            } else if (mode == 5) {
                const float* q0 = R + (size_t)r0 * N + c;
                const float* q1 = R + (size_t)(r0 + 8) * N + c;
                const float s0 = q0[0], s1 = q0[1], s2 = q1[0], s3 = q1[1];
                v0.x *= s0 / (1.f + __expf(-s0));
                v0.y *= s1 / (1.f + __expf(-s1));
                v1.x *= s2 / (1.f + __expf(-s2));
                v1.y *= s3 / (1.f + __expf(-s3));
            }
            if (Cf) {
                *(float2*)(Cf + (size_t)r0 * N + c) = v0;
                *(float2*)(Cf + (size_t)(r0 + 8) * N + c) = v1;
            }
            if (Chi) {
                __half2 h0 = __floats2half2_rn(v0.x, v0.y);
                __half2 h1 = __floats2half2_rn(v1.x, v1.y);
                float2 f0 = __half22float2(h0);
                float2 f1 = __half22float2(h1);
                __half2 l0 = __floats2half2_rn(v0.x - f0.x, v0.y - f0.y);
                __half2 l1 = __floats2half2_rn(v1.x - f1.x, v1.y - f1.y);
                *(__half2*)(Chi + (size_t)r0 * N + c) = h0;
                *(__half2*)(Chi + (size_t)(r0 + 8) * N + c) = h1;
                *(__half2*)(Clo + (size_t)r0 * N + c) = l0;
                *(__half2*)(Clo + (size_t)(r0 + 8) * N + c) = l1;
            }
        }
    }
}

// ---------------- rmsnorm: optional fp32 out + fp16 hi/lo split ----------------
__global__ __launch_bounds__(256) void rmsnorm_h_kernel(
    const float* __restrict__ x, const float* __restrict__ g,
    float* __restrict__ outf, __half2* __restrict__ hi, __half2* __restrict__ lo)
{
    __shared__ float red[8];
    __shared__ float sscale;
    const int row = blockIdx.x;
    const int t = threadIdx.x;
    const float4* xr = (const float4*)(x + (size_t)row * 1024);
    float4 v = xr[t];
    float ss = v.x*v.x + v.y*v.y + v.z*v.z + v.w*v.w;
#pragma unroll
    for (int o = 16; o; o >>= 1) ss += __shfl_xor_sync(0xffffffffu, ss, o);
    if ((t & 31) == 0) red[t >> 5] = ss;
    __syncthreads();
    if (t == 0) {
        float s = 0.f;
#pragma unroll
        for (int i = 0; i < 8; ++i) s += red[i];
        sscale = rsqrtf(s * (1.0f/1024.0f) + 1e-6f);
    }
    __syncthreads();
    const float sc = sscale;
    float4 gv = ((const float4*)g)[t];
    float4 o;
    o.x = v.x*sc*gv.x; o.y = v.y*sc*gv.y; o.z = v.z*sc*gv.z; o.w = v.w*sc*gv.w;
    if (outf) ((float4*)(outf + (size_t)row * 1024))[t] = o;
    __half2 h01 = __floats2half2_rn(o.x, o.y);
    __half2 h23 = __floats2half2_rn(o.z, o.w);
    float2 f01 = __half22float2(h01);
    float2 f23 = __half22float2(h23);
    __half2 l01 = __floats2half2_rn(o.x - f01.x, o.y - f01.y);
    __half2 l23 = __floats2half2_rn(o.z - f23.x, o.w - f23.y);
    const size_t p = (size_t)row * 512 + t * 2;
    hi[p] = h01; hi[p+1] = h23;
    lo[p] = l01; lo[p+1] = l23;
}

// ---------------- lambda ----------------
__global__ void lambda_kernel(const float* __restrict__ lq1, const float* __restrict__ lk1,
                              const float* __restrict__ lq2, const float* __restrict__ lk2,
                              float* __restrict__ lam)
{
    const int h = blockIdx.x;
    const int lane = threadIdx.x;
    float s1 = 0.f, s2 = 0.f;
    for (int d = lane; d < 64; d += 32) {
        s1 += lq1[h*64 + d] * lk1[h*64 + d];
        s2 += lq2[h*64 + d] * lk2[h*64 + d];
    }
#pragma unroll
    for (int o = 16; o; o >>= 1) {
        s1 += __shfl_xor_sync(0xffffffffu, s1, o);
        s2 += __shfl_xor_sync(0xffffffffu, s2, o);
    }
    if (lane == 0) lam[h] = expf(s1) - expf(s2) + 0.8f;
}

// ================ tensor-core flash diff-attention (bf16x3, fp16 split out) ================
#define FLM_ROWB 144u
#define SQ1H 0u
#define SQ2H 18432u
#define SK1H 36864u
#define SK2H 55296u
#define SVH  73728u
#define FLM_SMEM 92160
#define SOEX 36864u

__global__ __launch_bounds__(256, 2) void flash_mma_kernel(
    const float* __restrict__ Q, const float* __restrict__ Kg,
    const float* __restrict__ Vg, const float* __restrict__ lamp,
    __half* __restrict__ Ohi, __half* __restrict__ Olo,
    int Sq, int Sk, int causal)
{
    extern __shared__ char smf[];
    const uint32_t smb = smem_u32(smf);
    const int tid = threadIdx.x, wid = tid >> 5, lane = tid & 31;
    const int g = lane >> 2, qq = lane & 3;
    const int qt = blockIdx.x, h = blockIdx.y, b = blockIdx.z;
    const int mat = wid >> 2;
    const int slab = (wid & 3) * 16;

#pragma unroll
    for (int u = 0; u < 8; ++u) {
        const int idx = tid + u * 256;
        const int r = idx >> 5, d0 = (idx & 31) * 4;
        const float4 v = *(const float4*)(Q + ((size_t)(b*Sq + qt*64 + r) * Hh + h) * 128 + d0);
        const uint32_t off = ((d0 < 64) ? SQ1H : SQ2H) + (uint32_t)r * FLM_ROWB + (uint32_t)(d0 & 63) * 2;
        __nv_bfloat162 h01 = __floats2bfloat162_rn(v.x, v.y);
        __nv_bfloat162 h23 = __floats2bfloat162_rn(v.z, v.w);
        float2 f01 = __bfloat1622float2(h01), f23 = __bfloat1622float2(h23);
        __nv_bfloat162 l01 = __floats2bfloat162_rn(v.x - f01.x, v.y - f01.y);
        __nv_bfloat162 l23 = __floats2bfloat162_rn(v.z - f23.x, v.w - f23.y);
        *(__nv_bfloat162*)(smf + off)        = h01;
        *(__nv_bfloat162*)(smf + off + 4)    = h23;
        *(__nv_bfloat162*)(smf + off + 9216) = l01;
        *(__nv_bfloat162*)(smf + off + 9220) = l23;
    }

    float O[8][4];
#pragma unroll
    for (int t = 0; t < 8; ++t)
#pragma unroll
        for (int c = 0; c < 4; ++c) O[t][c] = 0.f;
    float rm[2] = { -1e30f, -1e30f }, rl[2] = { 0.f, 0.f };

    const int nkt = causal ? (qt + 1) : (Sk >> 6);

    for (int kt = 0; kt < nkt; ++kt) {
        __syncthreads();
#pragma unroll
        for (int u = 0; u < 8; ++u) {
            const int idx = tid + u * 256;
            const int r = idx >> 5, d0 = (idx & 31) * 4;
            const float4 v = *(const float4*)(Kg + ((size_t)(b*Sk + kt*64 + r) * Hh + h) * 128 + d0);
            const uint32_t off = ((d0 < 64) ? SK1H : SK2H) + (uint32_t)r * FLM_ROWB + (uint32_t)(d0 & 63) * 2;
            __nv_bfloat162 h01 = __floats2bfloat162_rn(v.x, v.y);
            __nv_bfloat162 h23 = __floats2bfloat162_rn(v.z, v.w);
            float2 f01 = __bfloat1622float2(h01), f23 = __bfloat1622float2(h23);
            __nv_bfloat162 l01 = __floats2bfloat162_rn(v.x - f01.x, v.y - f01.y);
            __nv_bfloat162 l23 = __floats2bfloat162_rn(v.z - f23.x, v.w - f23.y);
            *(__nv_bfloat162*)(smf + off)        = h01;
            *(__nv_bfloat162*)(smf + off + 4)    = h23;
            *(__nv_bfloat162*)(smf + off + 9216) = l01;
            *(__nv_bfloat162*)(smf + off + 9220) = l23;
        }
#pragma unroll
        for (int u = 0; u < 4; ++u) {
            const int idx = tid + u * 256;
            const int key = idx >> 4, d0 = (idx & 15) * 4;
            const float4 v = *(const float4*)(Vg + ((size_t)(b*Sk + kt*64 + key) * Hh + h) * 64 + d0);
            const float vv[4] = { v.x, v.y, v.z, v.w };
#pragma unroll
            for (int j = 0; j < 4; ++j) {
                const float f = vv[j];
                __nv_bfloat16 hb = __float2bfloat16(f);
                __nv_bfloat16 lb = __float2bfloat16(f - __bfloat162float(hb));
                const uint32_t o2 = (uint32_t)(d0 + j) * FLM_ROWB + (uint32_t)key * 2;
                *(__nv_bfloat16*)(smf + SVH + o2) = hb;
                *(__nv_bfloat16*)(smf + SVH + 9216 + o2) = lb;
            }
        }
        __syncthreads();

        float S[8][4];
#pragma unroll
        for (int t = 0; t < 8; ++t)
#pragma unroll
            for (int c = 0; c < 4; ++c) S[t][c] = 0.f;

        const uint32_t qB = smb + (mat ? SQ2H : SQ1H);
        const uint32_t kB = smb + (mat ? SK2H : SK1H);
#pragma unroll
        for (int s = 0; s < 4; ++s) {
            uint32_t ah[4], al[4];
            const uint32_t ao = qB + (uint32_t)(slab + g) * FLM_ROWB + s * 32 + qq * 4;
            ah[0] = lds32(ao);              ah[1] = lds32(ao + 8*FLM_ROWB);
            ah[2] = lds32(ao + 16);         ah[3] = lds32(ao + 8*FLM_ROWB + 16);
            al[0] = lds32(ao + 9216);       al[1] = lds32(ao + 9216 + 8*FLM_ROWB);
            al[2] = lds32(ao + 9216 + 16);  al[3] = lds32(ao + 9216 + 8*FLM_ROWB + 16);
#pragma unroll
            for (int nt = 0; nt < 8; ++nt) {
                const uint32_t bo = kB + (uint32_t)(nt*8 + g) * FLM_ROWB + s * 32 + qq * 4;
                uint32_t bh[2], bl[2];
                bh[0] = lds32(bo);        bh[1] = lds32(bo + 16);
                bl[0] = lds32(bo + 9216); bl[1] = lds32(bo + 9216 + 16);
                mma16816(S[nt], ah, bh);
                mma16816(S[nt], ah, bl);
                mma16816(S[nt], al, bh);
            }
        }

        const bool dg = (causal != 0) && (kt == qt);
        uint32_t pH[8][2], pL[8][2];
#pragma unroll
        for (int j = 0; j < 2; ++j) {
            const int rloc = slab + g + j*8;
            float mx = -1e30f;
#pragma unroll
            for (int t = 0; t < 8; ++t) {
                float* sp = &S[t][j*2];
                sp[0] *= 0.125f; sp[1] *= 0.125f;
                if (dg) {
                    const int c = t*8 + qq*2;
                    if (c > rloc)     sp[0] = -1e9f;
                    if (c + 1 > rloc) sp[1] = -1e9f;
                }
                mx = fmaxf(mx, fmaxf(sp[0], sp[1]));
            }
            mx = fmaxf(mx, __shfl_xor_sync(0xffffffffu, mx, 1));
            mx = fmaxf(mx, __shfl_xor_sync(0xffffffffu, mx, 2));
            const float mn = fmaxf(rm[j], mx);
            const float alw = __expf(rm[j] - mn);
            rm[j] = mn;
            float rs = 0.f;
#pragma unroll
            for (int t = 0; t < 8; ++t) {
                const float p0 = __expf(S[t][j*2]   - mn);
                const float p1 = __expf(S[t][j*2+1] - mn);
                rs += p0 + p1;
                __nv_bfloat162 hp = __floats2bfloat162_rn(p0, p1);
                float2 fp = __bfloat1622float2(hp);
                __nv_bfloat162 lp = __floats2bfloat162_rn(p0 - fp.x, p1 - fp.y);
                pH[t][j] = *(uint32_t*)&hp;
                pL[t][j] = *(uint32_t*)&lp;
            }
            rs += __shfl_xor_sync(0xffffffffu, rs, 1);
            rs += __shfl_xor_sync(0xffffffffu, rs, 2);
            rl[j] = rl[j] * alw + rs;
#pragma unroll
            for (int t = 0; t < 8; ++t) { O[t][j*2] *= alw; O[t][j*2+1] *= alw; }
        }

#pragma unroll
        for (int s = 0; s < 4; ++s) {
            const uint32_t aP[4]  = { pH[2*s][0], pH[2*s][1], pH[2*s+1][0], pH[2*s+1][1] };
            const uint32_t aPl[4] = { pL[2*s][0], pL[2*s][1], pL[2*s+1][0], pL[2*s+1][1] };
#pragma unroll
            for (int nt = 0; nt < 8; ++nt) {
                const uint32_t bo = smb + SVH + (uint32_t)(nt*8 + g) * FLM_ROWB + s * 32 + qq * 4;
                uint32_t bh[2], bl[2];
                bh[0] = lds32(bo);        bh[1] = lds32(bo + 16);
                bl[0] = lds32(bo + 9216); bl[1] = lds32(bo + 9216 + 16);
                mma16816(O[nt], aP,  bh);
                mma16816(O[nt], aP,  bl);
                mma16816(O[nt], aPl, bh);
            }
        }
    }

    __syncthreads();
    if (mat == 1) {
#pragma unroll
        for (int j = 0; j < 2; ++j) {
            const float inv = 1.f / rl[j];
            const int row = slab + g + j*8;
#pragma unroll
            for (int t = 0; t < 8; ++t) {
                const int col = t*8 + qq*2;
                float2 w = make_float2(O[t][j*2] * inv, O[t][j*2+1] * inv);
                *(float2*)(smf + SOEX + ((uint32_t)row * 68 + col) * 4) = w;
            }
        }
    }
    __syncthreads();
    if (mat == 0) {
        const float lam = lamp[h];
#pragma unroll
        for (int j = 0; j < 2; ++j) {
            const float inv = 1.f / rl[j];
            const int row = slab + g + j*8;
            float vbuf[16];
            float ss = 0.f;
#pragma unroll
            for (int t = 0; t < 8; ++t) {
                const int col = t*8 + qq*2;
                const float2 w = *(const float2*)(smf + SOEX + ((uint32_t)row * 68 + col) * 4);
                const float v0 = O[t][j*2]   * inv - lam * w.x;
                const float v1 = O[t][j*2+1] * inv - lam * w.y;
                vbuf[2*t] = v0; vbuf[2*t+1] = v1;
                ss += v0*v0 + v1*v1;
            }
            ss += __shfl_xor_sync(0xffffffffu, ss, 1);
            ss += __shfl_xor_sync(0xffffffffu, ss, 2);
            const float scl = rsqrtf(ss * (1.0f/64.0f) + 1e-6f) * 0.2f;
            const size_t ob = ((size_t)(b*Sq + qt*64 + row) * Hh + h) * 64;
#pragma unroll
            for (int t = 0; t < 8; ++t) {
                const int col = t*8 + qq*2;
                const float v0 = vbuf[2*t] * scl, v1 = vbuf[2*t+1] * scl;
                __half2 hh = __floats2half2_rn(v0, v1);
                float2 fh = __half22float2(hh);
                __half2 ll = __floats2half2_rn(v0 - fh.x, v1 - fh.y);
                *(__half2*)(Ohi + ob + col) = hh;
                *(__half2*)(Olo + ob + col) = ll;
            }
        }
    }
}

// ---------------- host-side launch helpers ----------------
static __half *s_wh, *s_ahi, *s_alo, *s_bhi, *s_blo;

static void splitWh(const float* W, uint32_t off, int K, int N) {
    split_t_h_kernel<<<dim3(N/32, K/32), dim3(32, 8)>>>(W, s_wh + off, K, N);
}
static void hgemm(const __half* ahi, const __half* alo, uint32_t woff,
                  const float* R, float* Cf, __half* chi, __half* clo,
                  int M, int N, int K, int mode)
{
    dim3 grid(N / 128, M / 128);
    hgemm_kernel<<<grid, 256, HG_SMEM>>>(ahi, alo, s_wh + woff,
                                         R, Cf, chi, clo, M, N, K, mode);
}

extern "C" void kernel_launch(void* const* d_in, const int* in_sizes, int n_in,
                              void* d_out, int out_size)
{
    const float* x    = (const float*)d_in[0];
    const float* enc  = (const float*)d_in[1];
    const float* Wq_s = (const float*)d_in[2];
    const float* Wk_s = (const float*)d_in[3];
    const float* Wv_s = (const float*)d_in[4];
    const float* Wo_s = (const float*)d_in[5];
    const float* lq1s = (const float*)d_in[6];
    const float* lk1s = (const float*)d_in[7];
    const float* lq2s = (const float*)d_in[8];
    const float* lk2s = (const float*)d_in[9];
    const float* Wq_c = (const float*)d_in[10];
    const float* Wk_c = (const float*)d_in[11];
    const float* Wv_c = (const float*)d_in[12];
    const float* Wo_c = (const float*)d_in[13];
    const float* lq1c = (const float*)d_in[14];
    const float* lk1c = (const float*)d_in[15];
    const float* lq2c = (const float*)d_in[16];
    const float* lk2c = (const float*)d_in[17];
    const float* grms = (const float*)d_in[18];
    const float* W1   = (const float*)d_in[19];
    const float* W2   = (const float*)d_in[20];
    const float* W3   = (const float*)d_in[21];
    float* out = (float*)d_out;

    float *hn, *q, *k, *v, *h2, *m1, *lam;
    cudaGetSymbolAddress((void**)&hn,  g_hn);
    cudaGetSymbolAddress((void**)&q,   g_q);
    cudaGetSymbolAddress((void**)&k,   g_k);
    cudaGetSymbolAddress((void**)&v,   g_v);
    cudaGetSymbolAddress((void**)&h2,  g_h2);
    cudaGetSymbolAddress((void**)&m1,  g_m1);
    cudaGetSymbolAddress((void**)&lam, g_lam);
    cudaGetSymbolAddress((void**)&s_wh,  g_wh);
    cudaGetSymbolAddress((void**)&s_ahi, g_ahi);
    cudaGetSymbolAddress((void**)&s_alo, g_alo);
    cudaGetSymbolAddress((void**)&s_bhi, g_bhi);
    cudaGetSymbolAddress((void**)&s_blo, g_blo);

    cudaFuncSetAttribute(flash_mma_kernel,
                         cudaFuncAttributeMaxDynamicSharedMemorySize, FLM_SMEM);
    cudaFuncSetAttribute(hgemm_kernel,
                         cudaFuncAttributeMaxDynamicSharedMemorySize, HG_SMEM);

    // ---- weight prep: single fp16 transposed ----
    splitWh(Wq_s, OW_QS, 1024, 2048);
    splitWh(Wk_s, OW_KS, 1024, 2048);
    splitWh(Wv_s, OW_VS, 1024, 1024);
    splitWh(Wo_s, OW_OS, 1024, 1024);
    splitWh(Wq_c, OW_QC, 1024, 2048);
    splitWh(Wk_c, OW_KC, 1024, 2048);
    splitWh(Wv_c, OW_VC, 1024, 1024);
    splitWh(Wo_c, OW_OC, 1024, 1024);
    splitWh(W1,   OW_W1, 1024, 4096);
    splitWh(W2,   OW_W2, 1024, 4096);
    splitWh(W3,   OW_W3, 4096, 1024);

    // h = rmsnorm(x, g) -> fp32 hn (residual) + fp16 split in A
    rmsnorm_h_kernel<<<ROWS, 256>>>(x, grms, hn, (__half2*)s_ahi, (__half2*)s_alo);

    // ---- self diff-attention (causal) ----
    hgemm(s_ahi, s_alo, OW_QS, nullptr, q, nullptr, nullptr, ROWS, 2048, 1024, 0);
    hgemm(s_ahi, s_alo, OW_KS, nullptr, k, nullptr, nullptr, ROWS, 2048, 1024, 0);
    hgemm(s_ahi, s_alo, OW_VS, nullptr, v, nullptr, nullptr, ROWS, 1024, 1024, 0);
    lambda_kernel<<<Hh, 32>>>(lq1s, lk1s, lq2s, lk2s, lam);
    flash_mma_kernel<<<dim3(Tt/64, Hh, Bb), 256, FLM_SMEM>>>(q, k, v, lam,
        s_bhi, s_blo, Tt, Tt, 1);
    // h1 = ao @ Wo_s + hn  -> fp16 split into A
    hgemm(s_bhi, s_blo, OW_OS, hn, nullptr, s_ahi, s_alo, ROWS, 1024, 1024, 1);

    // ---- cross diff-attention (not causal) ----
    hgemm(s_ahi, s_alo, OW_QC, nullptr, q, nullptr, nullptr, ROWS, 2048, 1024, 0);
    split_h_kernel<<<(ROWS*1024/4)/256, 256>>>((const float4*)enc,
        (__half2*)s_bhi, (__half2*)s_blo, ROWS*1024/4);
    hgemm(s_bhi, s_blo, OW_KC, nullptr, k, nullptr, nullptr, ROWS, 2048, 1024, 0);
    hgemm(s_bhi, s_blo, OW_VC, nullptr, v, nullptr, nullptr, ROWS, 1024, 1024, 0);
    lambda_kernel<<<Hh, 32>>>(lq1c, lk1c, lq2c, lk2c, lam + 16);
    flash_mma_kernel<<<dim3(Tt/64, Hh, Bb), 256, FLM_SMEM>>>(q, k, v, lam + 16,
        s_ahi, s_alo, Tt, Tt, 0);
    // h2 = 2 * (ao @ Wo_c) -> fp32 (residual + rmsnorm input)
    hgemm(s_ahi, s_alo, OW_OC, nullptr, h2, nullptr, nullptr, ROWS, 1024, 1024, 2);

    // ---- MLP (fp16 2-term path) ----
    rmsnorm_h_kernel<<<ROWS, 256>>>(h2, grms, nullptr, (__half2*)s_bhi, (__half2*)s_blo);
    hgemm(s_bhi, s_blo, OW_W1, nullptr, m1, nullptr, nullptr, ROWS, DFF, 1024, 0);
    hgemm(s_bhi, s_blo, OW_W2, m1, nullptr, s_ahi, s_alo, ROWS, DFF, 1024, 5);
    hgemm(s_ahi, s_alo, OW_W3, h2, out, nullptr, nullptr, ROWS, 1024, DFF, 1);
}

// round 12
// speedup vs baseline: 1.8153x; 1.0486x over previous
#include <cuda_runtime.h>
#include <cuda_bf16.h>
#include <cuda_fp16.h>
#include <math.h>
#include <stdint.h>

// ---------------- problem dims (fixed) ----------------
#define Bb   4
#define Tt   1024
#define Dd   1024
#define Hh   16
#define HSs  64
#define DFF  4096
#define ROWS (Bb*Tt)      // 4096

// ---------------- scratch (device globals; no allocs allowed) ----------------
__device__ float g_hn [ROWS*Dd];
__device__ float g_qkv[ROWS*5120];     // q(2048) | k(2048) | v(1024), row stride 5120
__device__ float g_h2 [ROWS*Dd];
__device__ float g_m1 [ROWS*DFF];
__device__ float g_lam[32];

// fp16 activation split buffers
#define NA_TOT (ROWS*DFF)
__device__ __half g_ahi[NA_TOT];
__device__ __half g_alo[NA_TOT];
__device__ __half g_bhi[NA_TOT];
__device__ __half g_blo[NA_TOT];

// fp16 weights (single term), transposed [N][K]
#define NHW_TOT (24u*1024u*1024u)
__device__ __half g_wh[NHW_TOT];
#define OW_QS (0u)
#define OW_KS (2u*1024u*1024u)
#define OW_VS (4u*1024u*1024u)
#define OW_OS (5u*1024u*1024u)
#define OW_QC (6u*1024u*1024u)
#define OW_KC (8u*1024u*1024u)
#define OW_VC (10u*1024u*1024u)
#define OW_OC (11u*1024u*1024u)
#define OW_W1 (12u*1024u*1024u)
#define OW_W2 (16u*1024u*1024u)
#define OW_W3 (20u*1024u*1024u)

// ================= small helpers =================
__device__ __forceinline__ uint32_t smem_u32(const void* p) {
    uint32_t a;
    asm("{ .reg .u64 t; cvta.to.shared.u64 t, %1; cvt.u32.u64 %0, t; }" : "=r"(a) : "l"(p));
    return a;
}
__device__ __forceinline__ void cp16(uint32_t dst, const void* src) {
    asm volatile("cp.async.cg.shared.global [%0], [%1], 16;" :: "r"(dst), "l"(src) : "memory");
}
__device__ __forceinline__ void cp_commit() {
    asm volatile("cp.async.commit_group;" ::: "memory");
}
__device__ __forceinline__ void cp_wait2() {
    asm volatile("cp.async.wait_group 2;" ::: "memory");
}
__device__ __forceinline__ void mma16816(float* d, const uint32_t* a, const uint32_t* b) {
    asm volatile(
        "mma.sync.aligned.m16n8k16.row.col.f32.bf16.bf16.f32 "
        "{%0,%1,%2,%3}, {%4,%5,%6,%7}, {%8,%9}, {%0,%1,%2,%3};"
        : "+f"(d[0]), "+f"(d[1]), "+f"(d[2]), "+f"(d[3])
        : "r"(a[0]), "r"(a[1]), "r"(a[2]), "r"(a[3]), "r"(b[0]), "r"(b[1]));
}
__device__ __forceinline__ void mma16816h(float* d, const uint32_t* a, const uint32_t* b) {
    asm volatile(
        "mma.sync.aligned.m16n8k16.row.col.f32.f16.f16.f32 "
        "{%0,%1,%2,%3}, {%4,%5,%6,%7}, {%8,%9}, {%0,%1,%2,%3};"
        : "+f"(d[0]), "+f"(d[1]), "+f"(d[2]), "+f"(d[3])
        : "r"(a[0]), "r"(a[1]), "r"(a[2]), "r"(a[3]), "r"(b[0]), "r"(b[1]));
}
__device__ __forceinline__ uint32_t lds32(uint32_t addr) {
    uint32_t v;
    asm volatile("ld.shared.b32 %0, [%1];" : "=r"(v) : "r"(addr));
    return v;
}

// ============ activation split: fp32 -> fp16 hi + fp16 lo ============
__global__ __launch_bounds__(256) void split_h_kernel(
    const float4* __restrict__ in, __half2* __restrict__ hi,
    __half2* __restrict__ lo, int n4)
{
    const int i = blockIdx.x * blockDim.x + threadIdx.x;
    if (i >= n4) return;
    float4 v = in[i];
    __half2 h01 = __floats2half2_rn(v.x, v.y);
    __half2 h23 = __floats2half2_rn(v.z, v.w);
    float2 f01 = __half22float2(h01);
    float2 f23 = __half22float2(h23);
    __half2 l01 = __floats2half2_rn(v.x - f01.x, v.y - f01.y);
    __half2 l23 = __floats2half2_rn(v.z - f23.x, v.w - f23.y);
    hi[2*i] = h01; hi[2*i+1] = h23;
    lo[2*i] = l01; lo[2*i+1] = l23;
}

// ============ weight transpose: single fp16 ============
__global__ __launch_bounds__(256) void split_t_h_kernel(
    const float* __restrict__ B, __half* __restrict__ th, int K, int N)
{
    __shared__ float tile[32][33];
    const int tx = threadIdx.x, ty = threadIdx.y;
    const int n0 = blockIdx.x * 32, k0 = blockIdx.y * 32;
#pragma unroll
    for (int j = ty; j < 32; j += 8)
        tile[j][tx] = B[(size_t)(k0 + j) * N + n0 + tx];
    __syncthreads();
#pragma unroll
    for (int j = ty; j < 32; j += 8) {
        const size_t o = (size_t)(n0 + j) * K + k0 + tx;
        th[o] = __float2half(tile[tx][j]);
    }
}

// ============ fp16x2 GEMM: A split hi/lo, W single fp16 ============
// mode 0: store fp32; 1: +R; 2: *2; 5: silu(R)*acc
// C row stride = ldc (also used for R); split outputs dense with stride ldc.
#define BG_ROWB   80
#define BG_BUF    (128*BG_ROWB)
#define HG_STAGE  (3*BG_BUF)
#define HG_SMEM   (3*HG_STAGE)

__global__ __launch_bounds__(256, 2) void hgemm_kernel(
    const __half* __restrict__ Ahi, const __half* __restrict__ Alo,
    const __half* __restrict__ W,
    const float* __restrict__ R, float* __restrict__ Cf,
    __half* __restrict__ Chi, __half* __restrict__ Clo,
    int M, int N, int K, int ldc, int mode)
{
    extern __shared__ char sm_c[];
    const uint32_t smb = smem_u32(sm_c);

    const int tid = threadIdx.x;
    const int wid = tid >> 5;
    const int lane = tid & 31;
    const int bm = blockIdx.y * 128, bn = blockIdx.x * 128;
    const int m0 = (wid >> 2) * 64;
    const int n0 = (wid & 3) * 32;
    const int qrow = lane >> 2;
    const int qk4 = (lane & 3) * 4;

    const int nch = K >> 5;

    auto issue_stage = [&](int t) {
        const int k0 = t * 32;
        const uint32_t sb = smb + (uint32_t)(t % 3) * HG_STAGE;
#pragma unroll
        for (int c = 0; c < 2; ++c) {
            const int idx = tid + c * 256;
            const int row = idx >> 2, q = idx & 3;
            const uint32_t so = (uint32_t)row * BG_ROWB + q * 16;
            const size_t goA = (size_t)(bm + row) * K + k0 + q * 8;
            const size_t goB = (size_t)(bn + row) * K + k0 + q * 8;
            cp16(sb + so,            Ahi + goA);
            cp16(sb + BG_BUF + so,   Alo + goA);
            cp16(sb + 2*BG_BUF + so, W + goB);
        }
        cp_commit();
    };

    issue_stage(0); issue_stage(1); issue_stage(2);

    float acc[4][4][4];
#pragma unroll
    for (int a = 0; a < 4; ++a)
#pragma unroll
        for (int b = 0; b < 4; ++b)
#pragma unroll
            for (int c = 0; c < 4; ++c) acc[a][b][c] = 0.f;

    for (int t = 0; t < nch; ++t) {
        cp_wait2();
        __syncthreads();
        const char* Ah = sm_c + (t % 3) * HG_STAGE;
        const char* Al = Ah + BG_BUF;
        const char* Bh = Ah + 2*BG_BUF;
#pragma unroll
        for (int kb = 0; kb <= 32; kb += 32) {
            uint32_t ahi[4][4], alo[4][4], bh[4][2];
#pragma unroll
            for (int mt = 0; mt < 4; ++mt) {
                const uint32_t off = (uint32_t)(m0 + mt*16 + qrow) * BG_ROWB + kb + qk4;
                ahi[mt][0] = *(const uint32_t*)(Ah + off);
                ahi[mt][1] = *(const uint32_t*)(Ah + off + 8*BG_ROWB);
                ahi[mt][2] = *(const uint32_t*)(Ah + off + 16);
                ahi[mt][3] = *(const uint32_t*)(Ah + off + 8*BG_ROWB + 16);
                alo[mt][0] = *(const uint32_t*)(Al + off);
                alo[mt][1] = *(const uint32_t*)(Al + off + 8*BG_ROWB);
                alo[mt][2] = *(const uint32_t*)(Al + off + 16);
                alo[mt][3] = *(const uint32_t*)(Al + off + 8*BG_ROWB + 16);
            }
#pragma unroll
            for (int nt = 0; nt < 4; ++nt) {
                const uint32_t off = (uint32_t)(n0 + nt*8 + qrow) * BG_ROWB + kb + qk4;
                bh[nt][0] = *(const uint32_t*)(Bh + off);
                bh[nt][1] = *(const uint32_t*)(Bh + off + 16);
            }
#pragma unroll
            for (int mt = 0; mt < 4; ++mt)
#pragma unroll
                for (int nt = 0; nt < 4; ++nt) {
                    mma16816h(acc[mt][nt], ahi[mt], bh[nt]);
                    mma16816h(acc[mt][nt], alo[mt], bh[nt]);
                }
        }
        __syncthreads();
        if (t + 3 < nch) issue_stage(t + 3);
        else cp_commit();
    }

#pragma unroll
    for (int mt = 0; mt < 4; ++mt) {
        const int r0 = bm + m0 + mt*16 + qrow;
#pragma unroll
        for (int nt = 0; nt < 4; ++nt) {
            const int c = bn + n0 + nt*8 + (lane & 3) * 2;
            float2 v0 = make_float2(acc[mt][nt][0], acc[mt][nt][1]);
            float2 v1 = make_float2(acc[mt][nt][2], acc[mt][nt][3]);
            if (mode == 1) {
                const float* q0 = R + (size_t)r0 * ldc + c;
                const float* q1 = R + (size_t)(r0 + 8) * ldc + c;
                v0.x += q0[0]; v0.y += q0[1];
                v1.x += q1[0]; v1.y += q1[1];
            } else if (mode == 2) {
                v0.x *= 2.f; v0.y *= 2.f; v1.x *= 2.f; v1.y *= 2.f;
            } else if (mode == 5) {
                const float* q0 = R + (size_t)r0 * ldc + c;
                const float* q1 = R + (size_t)(r0 + 8) * ldc + c;
                const float s0 = q0[0], s1 = q0[1], s2 = q1[0], s3 = q1[1];
                v0.x *= s0 / (1.f + __expf(-s0));
                v0.y *= s1 / (1.f + __expf(-s1));
                v1.x *= s2 / (1.f + __expf(-s2));
                v1.y *= s3 / (1.f + __expf(-s3));
            }
            if (Cf) {
                *(float2*)(Cf + (size_t)r0 * ldc + c) = v0;
                *(float2*)(Cf + (size_t)(r0 + 8) * ldc + c) = v1;
            }
            if (Chi) {
                __half2 h0 = __floats2half2_rn(v0.x, v0.y);
                __half2 h1 = __floats2half2_rn(v1.x, v1.y);
                float2 f0 = __half22float2(h0);
                float2 f1 = __half22float2(h1);
                __half2 l0 = __floats2half2_rn(v0.x - f0.x, v0.y - f0.y);
                __half2 l1 = __floats2half2_rn(v1.x - f1.x, v1.y - f1.y);
                *(__half2*)(Chi + (size_t)r0 * ldc + c) = h0;
                *(__half2*)(Chi + (size_t)(r0 + 8) * ldc + c) = h1;
                *(__half2*)(Clo + (size_t)r0 * ldc + c) = l0;
                *(__half2*)(Clo + (size_t)(r0 + 8) * ldc + c) = l1;
            }
        }
    }
}

// ---------------- rmsnorm: optional fp32 out + fp16 hi/lo split ----------------
__global__ __launch_bounds__(256) void rmsnorm_h_kernel(
    const float* __restrict__ x, const float* __restrict__ g,
    float* __restrict__ outf, __half2* __restrict__ hi, __half2* __restrict__ lo)
{
    __shared__ float red[8];
    __shared__ float sscale;
    const int row = blockIdx.x;
    const int t = threadIdx.x;
    const float4* xr = (const float4*)(x + (size_t)row * 1024);
    float4 v = xr[t];
    float ss = v.x*v.x + v.y*v.y + v.z*v.z + v.w*v.w;
#pragma unroll
    for (int o = 16; o; o >>= 1) ss += __shfl_xor_sync(0xffffffffu, ss, o);
    if ((t & 31) == 0) red[t >> 5] = ss;
    __syncthreads();
    if (t == 0) {
        float s = 0.f;
#pragma unroll
        for (int i = 0; i < 8; ++i) s += red[i];
        sscale = rsqrtf(s * (1.0f/1024.0f) + 1e-6f);
    }
    __syncthreads();
    const float sc = sscale;
    float4 gv = ((const float4*)g)[t];
    float4 o;
    o.x = v.x*sc*gv.x; o.y = v.y*sc*gv.y; o.z = v.z*sc*gv.z; o.w = v.w*sc*gv.w;
    if (outf) ((float4*)(outf + (size_t)row * 1024))[t] = o;
    __half2 h01 = __floats2half2_rn(o.x, o.y);
    __half2 h23 = __floats2half2_rn(o.z, o.w);
    float2 f01 = __half22float2(h01);
    float2 f23 = __half22float2(h23);
    __half2 l01 = __floats2half2_rn(o.x - f01.x, o.y - f01.y);
    __half2 l23 = __floats2half2_rn(o.z - f23.x, o.w - f23.y);
    const size_t p = (size_t)row * 512 + t * 2;
    hi[p] = h01; hi[p+1] = h23;
    lo[p] = l01; lo[p+1] = l23;
}

// ---------------- lambda ----------------
__global__ void lambda_kernel(const float* __restrict__ lq1, const float* __restrict__ lk1,
                              const float* __restrict__ lq2, const float* __restrict__ lk2,
                              float* __restrict__ lam)
{
    const int h = blockIdx.x;
    const int lane = threadIdx.x;
    float s1 = 0.f, s2 = 0.f;
    for (int d = lane; d < 64; d += 32) {
        s1 += lq1[h*64 + d] * lk1[h*64 + d];
        s2 += lq2[h*64 + d] * lk2[h*64 + d];
    }
#pragma unroll
    for (int o = 16; o; o >>= 1) {
        s1 += __shfl_xor_sync(0xffffffffu, s1, o);
        s2 += __shfl_xor_sync(0xffffffffu, s2, o);
    }
    if (lane == 0) lam[h] = expf(s1) - expf(s2) + 0.8f;
}

// ================ tensor-core flash diff-attention (bf16x3, fp16 split out) ================
// Q/K/V read from strided qkv buffer (row stride ldr floats)
#define FLM_ROWB 144u
#define SQ1H 0u
#define SQ2H 18432u
#define SK1H 36864u
#define SK2H 55296u
#define SVH  73728u
#define FLM_SMEM 92160
#define SOEX 36864u

__global__ __launch_bounds__(256, 2) void flash_mma_kernel(
    const float* __restrict__ Q, const float* __restrict__ Kg,
    const float* __restrict__ Vg, const float* __restrict__ lamp,
    __half* __restrict__ Ohi, __half* __restrict__ Olo,
    int Sq, int Sk, int causal, int ldr)
{
    extern __shared__ char smf[];
    const uint32_t smb = smem_u32(smf);
    const int tid = threadIdx.x, wid = tid >> 5, lane = tid & 31;
    const int g = lane >> 2, qq = lane & 3;
    const int qt = blockIdx.x, h = blockIdx.y, b = blockIdx.z;
    const int mat = wid >> 2;
    const int slab = (wid & 3) * 16;

#pragma unroll
    for (int u = 0; u < 8; ++u) {
        const int idx = tid + u * 256;
        const int r = idx >> 5, d0 = (idx & 31) * 4;
        const float4 v = *(const float4*)(Q + (size_t)(b*Sq + qt*64 + r) * ldr + h * 128 + d0);
        const uint32_t off = ((d0 < 64) ? SQ1H : SQ2H) + (uint32_t)r * FLM_ROWB + (uint32_t)(d0 & 63) * 2;
        __nv_bfloat162 h01 = __floats2bfloat162_rn(v.x, v.y);
        __nv_bfloat162 h23 = __floats2bfloat162_rn(v.z, v.w);
        float2 f01 = __bfloat1622float2(h01), f23 = __bfloat1622float2(h23);
        __nv_bfloat162 l01 = __floats2bfloat162_rn(v.x - f01.x, v.y - f01.y);
        __nv_bfloat162 l23 = __floats2bfloat162_rn(v.z - f23.x, v.w - f23.y);
        *(__nv_bfloat162*)(smf + off)        = h01;
        *(__nv_bfloat162*)(smf + off + 4)    = h23;
        *(__nv_bfloat162*)(smf + off + 9216) = l01;
        *(__nv_bfloat162*)(smf + off + 9220) = l23;
    }

    float O[8][4];
#pragma unroll
    for (int t = 0; t < 8; ++t)
#pragma unroll
        for (int c = 0; c < 4; ++c) O[t][c] = 0.f;
    float rm[2] = { -1e30f, -1e30f }, rl[2] = { 0.f, 0.f };

    const int nkt = causal ? (qt + 1) : (Sk >> 6);

    for (int kt = 0; kt < nkt; ++kt) {
        __syncthreads();
#pragma unroll
        for (int u = 0; u < 8; ++u) {
            const int idx = tid + u * 256;
            const int r = idx >> 5, d0 = (idx & 31) * 4;
            const float4 v = *(const float4*)(Kg + (size_t)(b*Sk + kt*64 + r) * ldr + h * 128 + d0);
            const uint32_t off = ((d0 < 64) ? SK1H : SK2H) + (uint32_t)r * FLM_ROWB + (uint32_t)(d0 & 63) * 2;
            __nv_bfloat162 h01 = __floats2bfloat162_rn(v.x, v.y);
            __nv_bfloat162 h23 = __floats2bfloat162_rn(v.z, v.w);
            float2 f01 = __bfloat1622float2(h01), f23 = __bfloat1622float2(h23);
            __nv_bfloat162 l01 = __floats2bfloat162_rn(v.x - f01.x, v.y - f01.y);
            __nv_bfloat162 l23 = __floats2bfloat162_rn(v.z - f23.x, v.w - f23.y);
            *(__nv_bfloat162*)(smf + off)        = h01;
            *(__nv_bfloat162*)(smf + off + 4)    = h23;
            *(__nv_bfloat162*)(smf + off + 9216) = l01;
            *(__nv_bfloat162*)(smf + off + 9220) = l23;
        }
#pragma unroll
        for (int u = 0; u < 4; ++u) {
            const int idx = tid + u * 256;
            const int key = idx >> 4, d0 = (idx & 15) * 4;
            const float4 v = *(const float4*)(Vg + (size_t)(b*Sk + kt*64 + key) * ldr + h * 64 + d0);
            const float vv[4] = { v.x, v.y, v.z, v.w };
#pragma unroll
            for (int j = 0; j < 4; ++j) {
                const float f = vv[j];
                __nv_bfloat16 hb = __float2bfloat16(f);
                __nv_bfloat16 lb = __float2bfloat16(f - __bfloat162float(hb));
                const uint32_t o2 = (uint32_t)(d0 + j) * FLM_ROWB + (uint32_t)key * 2;
                *(__nv_bfloat16*)(smf + SVH + o2) = hb;
                *(__nv_bfloat16*)(smf + SVH + 9216 + o2) = lb;
            }
        }
        __syncthreads();

        float S[8][4];
#pragma unroll
        for (int t = 0; t < 8; ++t)
#pragma unroll
            for (int c = 0; c < 4; ++c) S[t][c] = 0.f;

        const uint32_t qB = smb + (mat ? SQ2H : SQ1H);
        const uint32_t kB = smb + (mat ? SK2H : SK1H);
#pragma unroll
        for (int s = 0; s < 4; ++s) {
            uint32_t ah[4], al[4];
            const uint32_t ao = qB + (uint32_t)(slab + g) * FLM_ROWB + s * 32 + qq * 4;
            ah[0] = lds32(ao);              ah[1] = lds32(ao + 8*FLM_ROWB);
            ah[2] = lds32(ao + 16);         ah[3] = lds32(ao + 8*FLM_ROWB + 16);
            al[0] = lds32(ao + 9216);       al[1] = lds32(ao + 9216 + 8*FLM_ROWB);
            al[2] = lds32(ao + 9216 + 16);  al[3] = lds32(ao + 9216 + 8*FLM_ROWB + 16);
#pragma unroll
            for (int nt = 0; nt < 8; ++nt) {
                const uint32_t bo = kB + (uint32_t)(nt*8 + g) * FLM_ROWB + s * 32 + qq * 4;
                uint32_t bh[2], bl[2];
                bh[0] = lds32(bo);        bh[1] = lds32(bo + 16);
                bl[0] = lds32(bo + 9216); bl[1] = lds32(bo + 9216 + 16);
                mma16816(S[nt], ah, bh);
                mma16816(S[nt], ah, bl);
                mma16816(S[nt], al, bh);
            }
        }

        const bool dg = (causal != 0) && (kt == qt);
        uint32_t pH[8][2], pL[8][2];
#pragma unroll
        for (int j = 0; j < 2; ++j) {
            const int rloc = slab + g + j*8;
            float mx = -1e30f;
#pragma unroll
            for (int t = 0; t < 8; ++t) {
                float* sp = &S[t][j*2];
                sp[0] *= 0.125f; sp[1] *= 0.125f;
                if (dg) {
                    const int c = t*8 + qq*2;
                    if (c > rloc)     sp[0] = -1e9f;
                    if (c + 1 > rloc) sp[1] = -1e9f;
                }
                mx = fmaxf(mx, fmaxf(sp[0], sp[1]));
            }
            mx = fmaxf(mx, __shfl_xor_sync(0xffffffffu, mx, 1));
            mx = fmaxf(mx, __shfl_xor_sync(0xffffffffu, mx, 2));
            const float mn = fmaxf(rm[j], mx);
            const float alw = __expf(rm[j] - mn);
            rm[j] = mn;
            float rs = 0.f;
#pragma unroll
            for (int t = 0; t < 8; ++t) {
                const float p0 = __expf(S[t][j*2]   - mn);
                const float p1 = __expf(S[t][j*2+1] - mn);
                rs += p0 + p1;
                __nv_bfloat162 hp = __floats2bfloat162_rn(p0, p1);
                float2 fp = __bfloat1622float2(hp);
                __nv_bfloat162 lp = __floats2bfloat162_rn(p0 - fp.x, p1 - fp.y);
                pH[t][j] = *(uint32_t*)&hp;
                pL[t][j] = *(uint32_t*)&lp;
            }
            rs += __shfl_xor_sync(0xffffffffu, rs, 1);
            rs += __shfl_xor_sync(0xffffffffu, rs, 2);
            rl[j] = rl[j] * alw + rs;
#pragma unroll
            for (int t = 0; t < 8; ++t) { O[t][j*2] *= alw; O[t][j*2+1] *= alw; }
        }

#pragma unroll
        for (int s = 0; s < 4; ++s) {
            const uint32_t aP[4]  = { pH[2*s][0], pH[2*s][1], pH[2*s+1][0], pH[2*s+1][1] };
            const uint32_t aPl[4] = { pL[2*s][0], pL[2*s][1], pL[2*s+1][0], pL[2*s+1][1] };
#pragma unroll
            for (int nt = 0; nt < 8; ++nt) {
                const uint32_t bo = smb + SVH + (uint32_t)(nt*8 + g) * FLM_ROWB + s * 32 + qq * 4;
                uint32_t bh[2], bl[2];
                bh[0] = lds32(bo);        bh[1] = lds32(bo + 16);
                bl[0] = lds32(bo + 9216); bl[1] = lds32(bo + 9216 + 16);
                mma16816(O[nt], aP,  bh);
                mma16816(O[nt], aP,  bl);
                mma16816(O[nt], aPl, bh);
            }
        }
    }

    __syncthreads();
    if (mat == 1) {
#pragma unroll
        for (int j = 0; j < 2; ++j) {
            const float inv = 1.f / rl[j];
            const int row = slab + g + j*8;
#pragma unroll
            for (int t = 0; t < 8; ++t) {
                const int col = t*8 + qq*2;
                float2 w = make_float2(O[t][j*2] * inv, O[t][j*2+1] * inv);
                *(float2*)(smf + SOEX + ((uint32_t)row * 68 + col) * 4) = w;
            }
        }
    }
    __syncthreads();
    if (mat == 0) {
        const float lam = lamp[h];
#pragma unroll
        for (int j = 0; j < 2; ++j) {
            const float inv = 1.f / rl[j];
            const int row = slab + g + j*8;
            float vbuf[16];
            float ss = 0.f;
#pragma unroll
            for (int t = 0; t < 8; ++t) {
                const int col = t*8 + qq*2;
                const float2 w = *(const float2*)(smf + SOEX + ((uint32_t)row * 68 + col) * 4);
                const float v0 = O[t][j*2]   * inv - lam * w.x;
                const float v1 = O[t][j*2+1] * inv - lam * w.y;
                vbuf[2*t] = v0; vbuf[2*t+1] = v1;
                ss += v0*v0 + v1*v1;
            }
            ss += __shfl_xor_sync(0xffffffffu, ss, 1);
            ss += __shfl_xor_sync(0xffffffffu, ss, 2);
            const float scl = rsqrtf(ss * (1.0f/64.0f) + 1e-6f) * 0.2f;
            const size_t ob = ((size_t)(b*Sq + qt*64 + row) * Hh + h) * 64;
#pragma unroll
            for (int t = 0; t < 8; ++t) {
                const int col = t*8 + qq*2;
                const float v0 = vbuf[2*t] * scl, v1 = vbuf[2*t+1] * scl;
                __half2 hh = __floats2half2_rn(v0, v1);
                float2 fh = __half22float2(hh);
                __half2 ll = __floats2half2_rn(v0 - fh.x, v1 - fh.y);
                *(__half2*)(Ohi + ob + col) = hh;
                *(__half2*)(Olo + ob + col) = ll;
            }
        }
    }
}

// ---------------- host-side launch helpers ----------------
static __half *s_wh, *s_ahi, *s_alo, *s_bhi, *s_blo;

static void splitWh(const float* W, uint32_t off, int K, int N) {
    split_t_h_kernel<<<dim3(N/32, K/32), dim3(32, 8)>>>(W, s_wh + off, K, N);
}
static void hgemm(const __half* ahi, const __half* alo, uint32_t woff,
                  const float* R, float* Cf, __half* chi, __half* clo,
                  int M, int N, int K, int ldc, int mode)
{
    dim3 grid(N / 128, M / 128);
    hgemm_kernel<<<grid, 256, HG_SMEM>>>(ahi, alo, s_wh + woff,
                                         R, Cf, chi, clo, M, N, K, ldc, mode);
}

extern "C" void kernel_launch(void* const* d_in, const int* in_sizes, int n_in,
                              void* d_out, int out_size)
{
    const float* x    = (const float*)d_in[0];
    const float* enc  = (const float*)d_in[1];
    const float* Wq_s = (const float*)d_in[2];
    const float* Wk_s = (const float*)d_in[3];
    const float* Wv_s = (const float*)d_in[4];
    const float* Wo_s = (const float*)d_in[5];
    const float* lq1s = (const float*)d_in[6];
    const float* lk1s = (const float*)d_in[7];
    const float* lq2s = (const float*)d_in[8];
    const float* lk2s = (const float*)d_in[9];
    const float* Wq_c = (const float*)d_in[10];
    const float* Wk_c = (const float*)d_in[11];
    const float* Wv_c = (const float*)d_in[12];
    const float* Wo_c = (const float*)d_in[13];
    const float* lq1c = (const float*)d_in[14];
    const float* lk1c = (const float*)d_in[15];
    const float* lq2c = (const float*)d_in[16];
    const float* lk2c = (const float*)d_in[17];
    const float* grms = (const float*)d_in[18];
    const float* W1   = (const float*)d_in[19];
    const float* W2   = (const float*)d_in[20];
    const float* W3   = (const float*)d_in[21];
    float* out = (float*)d_out;

    float *hn, *qkv, *h2, *m1, *lam;
    cudaGetSymbolAddress((void**)&hn,  g_hn);
    cudaGetSymbolAddress((void**)&qkv, g_qkv);
    cudaGetSymbolAddress((void**)&h2,  g_h2);
    cudaGetSymbolAddress((void**)&m1,  g_m1);
    cudaGetSymbolAddress((void**)&lam, g_lam);
    cudaGetSymbolAddress((void**)&s_wh,  g_wh);
    cudaGetSymbolAddress((void**)&s_ahi, g_ahi);
    cudaGetSymbolAddress((void**)&s_alo, g_alo);
    cudaGetSymbolAddress((void**)&s_bhi, g_bhi);
    cudaGetSymbolAddress((void**)&s_blo, g_blo);

    cudaFuncSetAttribute(flash_mma_kernel,
                         cudaFuncAttributeMaxDynamicSharedMemorySize, FLM_SMEM);
    cudaFuncSetAttribute(hgemm_kernel,
                         cudaFuncAttributeMaxDynamicSharedMemorySize, HG_SMEM);

    // ---- weight prep: single fp16 transposed ----
    splitWh(Wq_s, OW_QS, 1024, 2048);
    splitWh(Wk_s, OW_KS, 1024, 2048);
    splitWh(Wv_s, OW_VS, 1024, 1024);
    splitWh(Wo_s, OW_OS, 1024, 1024);
    splitWh(Wq_c, OW_QC, 1024, 2048);
    splitWh(Wk_c, OW_KC, 1024, 2048);
    splitWh(Wv_c, OW_VC, 1024, 1024);
    splitWh(Wo_c, OW_OC, 1024, 1024);
    splitWh(W1,   OW_W1, 1024, 4096);
    splitWh(W2,   OW_W2, 1024, 4096);
    splitWh(W3,   OW_W3, 4096, 1024);

    // h = rmsnorm(x, g) -> fp32 hn (residual) + fp16 split in A
    rmsnorm_h_kernel<<<ROWS, 256>>>(x, grms, hn, (__half2*)s_ahi, (__half2*)s_alo);

    // ---- self diff-attention (causal): merged QKV GEMM (N=5120) ----
    hgemm(s_ahi, s_alo, OW_QS, nullptr, qkv, nullptr, nullptr, ROWS, 5120, 1024, 5120, 0);
    lambda_kernel<<<Hh, 32>>>(lq1s, lk1s, lq2s, lk2s, lam);
    flash_mma_kernel<<<dim3(Tt/64, Hh, Bb), 256, FLM_SMEM>>>(qkv, qkv + 2048, qkv + 4096,
        lam, s_bhi, s_blo, Tt, Tt, 1, 5120);
    // h1 = ao @ Wo_s + hn  -> fp16 split into A
    hgemm(s_bhi, s_blo, OW_OS, hn, nullptr, s_ahi, s_alo, ROWS, 1024, 1024, 1024, 1);

    // ---- cross diff-attention (not causal) ----
    hgemm(s_ahi, s_alo, OW_QC, nullptr, qkv, nullptr, nullptr, ROWS, 2048, 1024, 5120, 0);
    split_h_kernel<<<(ROWS*1024/4)/256, 256>>>((const float4*)enc,
        (__half2*)s_bhi, (__half2*)s_blo, ROWS*1024/4);
    // merged K|V GEMM (N=3072) into qkv cols 2048..5119
    hgemm(s_bhi, s_blo, OW_KC, nullptr, qkv + 2048, nullptr, nullptr, ROWS, 3072, 1024, 5120, 0);
    lambda_kernel<<<Hh, 32>>>(lq1c, lk1c, lq2c, lk2c, lam + 16);
    flash_mma_kernel<<<dim3(Tt/64, Hh, Bb), 256, FLM_SMEM>>>(qkv, qkv + 2048, qkv + 4096,
        lam + 16, s_ahi, s_alo, Tt, Tt, 0, 5120);
    // h2 = 2 * (ao @ Wo_c) -> fp32 (residual + rmsnorm input)
    hgemm(s_ahi, s_alo, OW_OC, nullptr, h2, nullptr, nullptr, ROWS, 1024, 1024, 1024, 2);

    // ---- MLP (fp16 2-term path) ----
    rmsnorm_h_kernel<<<ROWS, 256>>>(h2, grms, nullptr, (__half2*)s_bhi, (__half2*)s_blo);
    hgemm(s_bhi, s_blo, OW_W1, nullptr, m1, nullptr, nullptr, ROWS, DFF, 1024, DFF, 0);
    hgemm(s_bhi, s_blo, OW_W2, m1, nullptr, s_ahi, s_alo, ROWS, DFF, 1024, DFF, 5);
    hgemm(s_ahi, s_alo, OW_W3, h2, out, nullptr, nullptr, ROWS, 1024, DFF, 1024, 1);
}